// round 13
// baseline (speedup 1.0000x reference)
#include <cuda_runtime.h>
#include <cuda_fp16.h>
#include <stdint.h>

#define HW    60
#define NPIX  3600
#define HIDC  64
#define FEATC 128
#define MSIZE (3600LL*3600LL)
#define SEG   8
#define SEGN  450   /* 3600/8 */
#define NTIL  29    /* ceil(3600/128) */
#define PIXB  64    /* pixels per bwdconv1 block */
#define FBLK  60    /* final partial blocks */

// ---------------- static device scratch (no allocations allowed) ----------------
__device__ float g_xw[16*3*NPIX];            // forward-warped inputs
__device__ float g_h1[16L*NPIX*HIDC];        // conv3x3+relu, TRANSPOSED: [ib][pix][ch]
__device__ __half g_Fh[16L*NPIX*FEATC];      // features (fp16)
__device__ __half g_M [8L*3600*3600];        // [mat*4+b][n][m]  fp16 (~207MB)
__device__ float g_rmax_p[NTIL*4*NPIX], g_rsum_p[NTIL*4*NPIX];
__device__ float g_cmax_p[NTIL*4*NPIX], g_csum_p[NTIL*4*NPIX];
__device__ float g_hmax[4*NPIX], g_hs[4*NPIX];
__device__ float g_vmax[4*NPIX], g_vs[4*NPIX];
__device__ float g_Spart[SEG*4*NPIX];
__device__ float g_fpart[FBLK];

// Fast exp on the FMA pipe (no MUFU). rel err ~2e-5.
__device__ __forceinline__ float fexp(float x) {
    float t = x * 1.4426950408889634f;
    t = fmaxf(t, -125.0f);
    float r = floorf(t);
    float f = t - r;
    float p = 1.5403530e-4f;
    p = fmaf(p, f, 1.3333558e-3f);
    p = fmaf(p, f, 9.6181291e-3f);
    p = fmaf(p, f, 5.5504109e-2f);
    p = fmaf(p, f, 2.4022651e-1f);
    p = fmaf(p, f, 6.9314718e-1f);
    p = fmaf(p, f, 1.0f);
    int ei = (int)r;
    return __int_as_float((ei + 127) << 23) * p;
}

__device__ __forceinline__ void compute_theta(const float* __restrict__ noise, int swp, int ib,
                                              float* TA, float* TB) {
    const float* nz = noise + ib * 9;
    float a  = 1.f + 0.05f * nz[0], b = 0.05f * nz[1], c = 0.05f * nz[2];
    float d  = 0.05f * nz[3], e = 1.f + 0.05f * nz[4], f = 0.05f * nz[5];
    float id = 1.f / (a * e - b * d);
    float fwd[6] = {a, b, c, d, e, f};
    float bwd[6] = { e * id, -b * id, (b * f - c * e) * id,
                    -d * id,  a * id, (c * d - a * f) * id};
    bool s = (swp == 1);
#pragma unroll
    for (int k = 0; k < 6; k++) {
        if (TA) TA[k] = s ? bwd[k] : fwd[k];
        if (TB) TB[k] = s ? fwd[k] : bwd[k];
    }
}

// ---------------- K1: forward grid_sample ----------------
__global__ void fwd_sample_kernel(const float* __restrict__ inA, const float* __restrict__ inB,
                                  const float* __restrict__ noise, const int* __restrict__ swap,
                                  const int* __restrict__ u_roll, const int* __restrict__ v_roll) {
    int idx = blockIdx.x * blockDim.x + threadIdx.x;
    if (idx >= 16 * 3 * NPIX) return;
    int p  = idx % NPIX;
    int c  = (idx / NPIX) % 3;
    int ib = idx / (3 * NPIX);
    int i  = ib >> 2, b = ib & 3;
    float T[6];
    compute_theta(noise, swap[i], ib, T, nullptr);
    int r = p / HW, cc = p % HW;
    float xn = (2 * cc + 1) * (1.f / HW) - 1.f;
    float yn = (2 * r  + 1) * (1.f / HW) - 1.f;
    float gx = T[0] * xn + T[1] * yn + T[2];
    float gy = T[3] * xn + T[4] * yn + T[5];
    float x = (gx + 1.f) * (HW * 0.5f) - 0.5f;
    float y = (gy + 1.f) * (HW * 0.5f) - 0.5f;
    float x0f = floorf(x), y0f = floorf(y);
    int x0 = (int)x0f, y0 = (int)y0f;
    float wx1 = x - x0f, wx0 = 1.f - wx1;
    float wy1 = y - y0f, wy0 = 1.f - wy1;
    const float* src = ((i & 1) == 0) ? inA : inB;
    src += (b * 3 + c) * NPIX;
    int u = u_roll[ib], v = v_roll[ib];
    float acc = 0.f;
#pragma unroll
    for (int ky = 0; ky < 2; ky++) {
        int iy = y0 + ky;
        if (iy < 0 || iy >= HW) continue;
        int ry = iy + u; if (ry >= HW) ry -= HW;
        float wy = ky ? wy1 : wy0;
#pragma unroll
        for (int kx = 0; kx < 2; kx++) {
            int ix = x0 + kx;
            if (ix < 0 || ix >= HW) continue;
            int rx = ix + v; if (rx >= HW) rx -= HW;
            acc += wy * (kx ? wx1 : wx0) * src[ry * HW + rx];
        }
    }
    g_xw[ib * 3 * NPIX + c * NPIX + p] = acc;
}

// ---------------- K2: conv3x3 (3->64) + relu, transposed out ----------------
__global__ void conv3_kernel(const float* __restrict__ w1, const float* __restrict__ b1) {
    int idx = blockIdx.x * blockDim.x + threadIdx.x;
    if (idx >= 16 * HIDC * NPIX) return;
    int p  = idx % NPIX;
    int oc = (idx / NPIX) % HIDC;
    int ib = idx / (NPIX * HIDC);
    int r = p / HW, c = p % HW;
    const float* xin = g_xw + ib * 3 * NPIX;
    const float* wk  = w1 + oc * 27;
    float acc = b1[oc];
#pragma unroll
    for (int ci = 0; ci < 3; ci++)
#pragma unroll
        for (int dy = -1; dy <= 1; dy++) {
            int rr = r + dy;
            if (rr < 0 || rr >= HW) continue;
#pragma unroll
            for (int dx = -1; dx <= 1; dx++) {
                int c2 = c + dx;
                if (c2 < 0 || c2 >= HW) continue;
                acc += wk[ci * 9 + (dy + 1) * 3 + (dx + 1)] * xin[ci * NPIX + rr * HW + c2];
            }
        }
    g_h1[((size_t)ib * NPIX + p) * HIDC + oc] = fmaxf(acc, 0.f);
}

// ---------------- K3: fused backward grid_sample + conv1x1 (dynamic smem) ----------------
#define BW_W2S   0
#define BW_HS    (FEATC * 65)
#define BW_WTS   (BW_HS + PIXB * 68)
#define BW_WSS   (BW_WTS + PIXB * 4)
#define BW_PPS   (BW_WSS + PIXB)
#define BW_SMEM  ((BW_PPS + PIXB * 4) * 4)
__global__ __launch_bounds__(256) void bwdconv1_kernel(
        const float* __restrict__ w2, const float* __restrict__ b2,
        const float* __restrict__ noise, const int* __restrict__ swap,
        const int* __restrict__ u_roll, const int* __restrict__ v_roll) {
    extern __shared__ float smf[];
    float* w2s = smf + BW_W2S;
    float* Hs  = smf + BW_HS;
    float* wts = smf + BW_WTS;
    float* wss = smf + BW_WSS;
    int*   pps = (int*)(smf + BW_PPS);

    int ib = blockIdx.y;
    int p0 = blockIdx.x * PIXB;
    int tid = threadIdx.x;

    for (int i = tid; i < FEATC * HIDC; i += 256)
        w2s[(i >> 6) * 65 + (i & 63)] = w2[i];

    if (tid < PIXB) {
        int gp = p0 + tid;
        float T[6];
        compute_theta(noise, swap[ib >> 2], ib, nullptr, T);
        int u = u_roll[ib], v = v_roll[ib];
        int n = (gp < NPIX) ? gp : NPIX - 1;
        int r = n / HW, c = n % HW;
        int rr = r - u; if (rr < 0) rr += HW;
        int cc = c - v; if (cc < 0) cc += HW;
        float xn = (2 * cc + 1) * (1.f / HW) - 1.f;
        float yn = (2 * rr + 1) * (1.f / HW) - 1.f;
        float gx = T[0] * xn + T[1] * yn + T[2];
        float gy = T[3] * xn + T[4] * yn + T[5];
        float x = (gx + 1.f) * (HW * 0.5f) - 0.5f;
        float y = (gy + 1.f) * (HW * 0.5f) - 0.5f;
        float x0f = floorf(x), y0f = floorf(y);
        int x0 = (int)x0f, y0 = (int)y0f;
        float wx1 = x - x0f, wx0 = 1.f - wx1;
        float wy1 = y - y0f, wy0 = 1.f - wy1;
        float ws = 0.f;
#pragma unroll
        for (int k = 0; k < 4; k++) {
            int iy = y0 + (k >> 1), ix = x0 + (k & 1);
            bool ok = (iy >= 0 && iy < HW && ix >= 0 && ix < HW) && (gp < NPIX);
            pps[tid * 4 + k] = ok ? (iy * HW + ix) : -1;
            float w = ((k >> 1) ? wy1 : wy0) * ((k & 1) ? wx1 : wx0);
            wts[tid * 4 + k] = w;
            if (ok) ws += w;
        }
        wss[tid] = ws;
    }
    __syncthreads();

    const float* hb = g_h1 + (size_t)ib * NPIX * HIDC;
#pragma unroll
    for (int e = 0; e < 16; e++) {
        int idx = tid + e * 256;
        int ch = idx & 63, pix = idx >> 6;
        float a = 0.f;
#pragma unroll
        for (int k = 0; k < 4; k++) {
            int q = pps[pix * 4 + k];
            if (q >= 0) a += wts[pix * 4 + k] * hb[(size_t)q * HIDC + ch];
        }
        Hs[pix * 68 + ch] = a;
    }
    __syncthreads();

    int d = tid & 127;
    float wreg[HIDC];
#pragma unroll
    for (int h = 0; h < HIDC; h++) wreg[h] = w2s[d * 65 + h];
    float bd = b2[d];

#pragma unroll 4
    for (int pass = 0; pass < 32; pass++) {
        int pix = pass * 2 + (tid >> 7);
        int gp = p0 + pix;
        float acc = wss[pix] * bd;
        const float4* hv = (const float4*)&Hs[pix * 68];
#pragma unroll
        for (int h4 = 0; h4 < 16; h4++) {
            float4 hvv = hv[h4];
            acc = fmaf(wreg[h4 * 4 + 0], hvv.x, acc);
            acc = fmaf(wreg[h4 * 4 + 1], hvv.y, acc);
            acc = fmaf(wreg[h4 * 4 + 2], hvv.z, acc);
            acc = fmaf(wreg[h4 * 4 + 3], hvv.w, acc);
        }
        if (gp < NPIX)
            g_Fh[((size_t)ib * NPIX + gp) * FEATC + d] = __float2half_rn(acc);
    }
}

// ---------------- K4: single-term fp16 HMMA GEMM, 128x128, fp16 C ----------------
#define SA_HI 0
#define SBH_OFF 32768
#define GEMM_SMEM 65536
__device__ __forceinline__ uint32_t sw_off(int r, int c16) {
    return (uint32_t)(r * 256 + ((((c16 ^ r) & 7)) | (c16 & 8)) * 16);
}
__device__ __forceinline__ uint32_t smem_u32(const void* p) {
    uint32_t a;
    asm("{ .reg .u64 t; cvta.to.shared.u64 t, %1; cvt.u32.u64 %0, t; }" : "=r"(a) : "l"(p));
    return a;
}
#define LDSM_X4(R0, R1, R2, R3, addr)                                             \
    asm volatile("ldmatrix.sync.aligned.m8n8.x4.shared.b16 {%0,%1,%2,%3}, [%4];"  \
                 : "=r"(R0), "=r"(R1), "=r"(R2), "=r"(R3) : "r"(addr))
#define HMMA16816(D, A0, A1, A2, A3, B0, B1)                                      \
    asm volatile("mma.sync.aligned.m16n8k16.row.col.f32.f16.f16.f32 "             \
                 "{%0,%1,%2,%3}, {%4,%5,%6,%7}, {%8,%9}, {%0,%1,%2,%3};\n"        \
                 : "+f"(D[0]), "+f"(D[1]), "+f"(D[2]), "+f"(D[3])                 \
                 : "r"(A0), "r"(A1), "r"(A2), "r"(A3), "r"(B0), "r"(B1))

__global__ __launch_bounds__(256, 2) void gemm_hmma_kernel() {
    extern __shared__ char smem[];
    uint32_t sb = smem_u32(smem);
    int z = blockIdx.z;
    int mat = z >> 2, b = z & 3;
    size_t baseA = (size_t)((mat * 2)     * 4 + b) * NPIX * FEATC;
    size_t baseB = (size_t)((mat * 2 + 1) * 4 + b) * NPIX * FEATC;
    __half* C = g_M + (size_t)z * MSIZE;
    int n0 = blockIdx.y * 128, m0 = blockIdx.x * 128;
    int tid = threadIdx.x;
    int wid = tid >> 5, lane = tid & 31;
    int wr = wid >> 2, wc = wid & 3;

    // ---- copy A, B (2 x 2048 uint4) ----
    {
        const uint4* srcA = (const uint4*)(g_Fh + baseA);
        const uint4* srcB = (const uint4*)(g_Fh + baseB);
#pragma unroll
        for (int i = 0; i < 8; i++) {
            int slot = tid + i * 256;
            int c16 = slot & 15, row = slot >> 4;
            int gr = n0 + row, gm = m0 + row;
            uint4 va = make_uint4(0, 0, 0, 0), vb = va;
            if (gr < NPIX) va = srcA[gr * 16 + c16];
            if (gm < NPIX) vb = srcB[gm * 16 + c16];
            uint32_t o = sw_off(row, c16);
            *(uint4*)(smem + SA_HI  + o) = va;
            *(uint4*)(smem + SBH_OFF + o) = vb;
        }
    }
    __syncthreads();

    float acc[4][4][4];
#pragma unroll
    for (int u = 0; u < 4; u++)
#pragma unroll
        for (int v = 0; v < 4; v++)
#pragma unroll
            for (int r = 0; r < 4; r++) acc[u][v][r] = 0.f;

    int a_row_l = ((lane >> 3) & 1) * 8 + (lane & 7);
    int a_c16_l = (lane >> 4);
    int b_row_l = ((lane >> 4) * 8) + (lane & 7);
    int b_c16_l = ((lane >> 3) & 1);

    // hoisted base addresses; per-kt address = base ^ (kt<<5)  (swizzle XOR identity)
    uint32_t aB[4], bB[2];
#pragma unroll
    for (int mt = 0; mt < 4; mt++)
        aB[mt] = sb + SA_HI + sw_off(wr * 64 + mt * 16 + a_row_l, a_c16_l);
#pragma unroll
    for (int np = 0; np < 2; np++)
        bB[np] = sb + SBH_OFF + sw_off(wc * 32 + np * 16 + b_row_l, b_c16_l);

#pragma unroll
    for (int kt = 0; kt < 8; kt++) {
        uint32_t x = (uint32_t)kt << 5;
        uint32_t ah[4][4], bh[4][2];
#pragma unroll
        for (int mt = 0; mt < 4; mt++)
            LDSM_X4(ah[mt][0], ah[mt][1], ah[mt][2], ah[mt][3], aB[mt] ^ x);
#pragma unroll
        for (int np = 0; np < 2; np++)
            LDSM_X4(bh[np * 2][0], bh[np * 2][1], bh[np * 2 + 1][0], bh[np * 2 + 1][1], bB[np] ^ x);
#pragma unroll
        for (int mt = 0; mt < 4; mt++)
#pragma unroll
            for (int nt = 0; nt < 4; nt++)
                HMMA16816(acc[mt][nt], ah[mt][0], ah[mt][1], ah[mt][2], ah[mt][3], bh[nt][0], bh[nt][1]);
    }

    // ---- store C (fp16, streaming) ----
    int g = lane >> 2, t4 = lane & 3;
    bool full = (n0 + 128 <= NPIX) && (m0 + 128 <= NPIX);
    if (full) {
#pragma unroll
        for (int mt = 0; mt < 4; mt++) {
            __half* C0 = C + (size_t)(n0 + wr * 64 + mt * 16 + g) * NPIX + (m0 + wc * 32 + 2 * t4);
            __half* C1 = C0 + 8 * NPIX;
#pragma unroll
            for (int nt = 0; nt < 4; nt++) {
                __stcs((__half2*)(C0 + nt * 8), __floats2half2_rn(acc[mt][nt][0], acc[mt][nt][1]));
                __stcs((__half2*)(C1 + nt * 8), __floats2half2_rn(acc[mt][nt][2], acc[mt][nt][3]));
            }
        }
    } else {
#pragma unroll
        for (int mt = 0; mt < 4; mt++) {
            int r0 = n0 + wr * 64 + mt * 16 + g;
#pragma unroll
            for (int nt = 0; nt < 4; nt++) {
                int col = m0 + wc * 32 + nt * 8 + 2 * t4;
                if (col < NPIX) {
                    if (r0 < NPIX)
                        *(__half2*)&C[(size_t)r0 * NPIX + col] = __floats2half2_rn(acc[mt][nt][0], acc[mt][nt][1]);
                    if (r0 + 8 < NPIX)
                        *(__half2*)&C[(size_t)(r0 + 8) * NPIX + col] = __floats2half2_rn(acc[mt][nt][2], acc[mt][nt][3]);
                }
            }
        }
    }

    // ---- fused per-tile softmax stats ----
    __syncthreads();
    float* s_a   = (float*)smem;
    float* s_fin = (float*)smem + 512;

    if (mat == 0) {
        float rmx[4][2];
#pragma unroll
        for (int mt = 0; mt < 4; mt++)
#pragma unroll
            for (int h = 0; h < 2; h++) {
                float v = -1e30f;
#pragma unroll
                for (int nt = 0; nt < 4; nt++)
#pragma unroll
                    for (int k = 0; k < 2; k++) {
                        int col = m0 + wc * 32 + nt * 8 + 2 * t4 + k;
                        float x = (col < NPIX) ? acc[mt][nt][h * 2 + k] : -1e30f;
                        v = fmaxf(v, x);
                    }
                rmx[mt][h] = v;
            }
#pragma unroll
        for (int o = 1; o < 4; o <<= 1)
#pragma unroll
            for (int mt = 0; mt < 4; mt++)
#pragma unroll
                for (int h = 0; h < 2; h++)
                    rmx[mt][h] = fmaxf(rmx[mt][h], __shfl_xor_sync(0xffffffffu, rmx[mt][h], o));
        if (t4 == 0)
#pragma unroll
            for (int mt = 0; mt < 4; mt++)
#pragma unroll
                for (int h = 0; h < 2; h++)
                    s_a[wc * 128 + wr * 64 + mt * 16 + h * 8 + g] = rmx[mt][h];
        __syncthreads();
        if (tid < 128)
            s_fin[tid] = fmaxf(fmaxf(s_a[tid], s_a[128 + tid]), fmaxf(s_a[256 + tid], s_a[384 + tid]));
        __syncthreads();
        float rsm[4][2];
#pragma unroll
        for (int mt = 0; mt < 4; mt++)
#pragma unroll
            for (int h = 0; h < 2; h++) {
                float fm = s_fin[wr * 64 + mt * 16 + h * 8 + g];
                float sa = 0.f;
#pragma unroll
                for (int nt = 0; nt < 4; nt++)
#pragma unroll
                    for (int k = 0; k < 2; k++) {
                        int col = m0 + wc * 32 + nt * 8 + 2 * t4 + k;
                        float x = (col < NPIX) ? acc[mt][nt][h * 2 + k] : -1e30f;
                        sa += fexp(x - fm);
                    }
                rsm[mt][h] = sa;
            }
#pragma unroll
        for (int o = 1; o < 4; o <<= 1)
#pragma unroll
            for (int mt = 0; mt < 4; mt++)
#pragma unroll
                for (int h = 0; h < 2; h++)
                    rsm[mt][h] += __shfl_xor_sync(0xffffffffu, rsm[mt][h], o);
        __syncthreads();
        if (t4 == 0)
#pragma unroll
            for (int mt = 0; mt < 4; mt++)
#pragma unroll
                for (int h = 0; h < 2; h++)
                    s_a[wc * 128 + wr * 64 + mt * 16 + h * 8 + g] = rsm[mt][h];
        __syncthreads();
        if (tid < 128) {
            int n = n0 + tid;
            if (n < NPIX) {
                int o = (blockIdx.x * 4 + b) * NPIX + n;
                g_rmax_p[o] = s_fin[tid];
                g_rsum_p[o] = s_a[tid] + s_a[128 + tid] + s_a[256 + tid] + s_a[384 + tid];
            }
        }
    } else {
        float cmx[4][2];
#pragma unroll
        for (int nt = 0; nt < 4; nt++)
#pragma unroll
            for (int k = 0; k < 2; k++) {
                float v = -1e30f;
#pragma unroll
                for (int mt = 0; mt < 4; mt++)
#pragma unroll
                    for (int h = 0; h < 2; h++) {
                        int row = n0 + wr * 64 + mt * 16 + h * 8 + g;
                        float x = (row < NPIX) ? acc[mt][nt][h * 2 + k] : -1e30f;
                        v = fmaxf(v, x);
                    }
                cmx[nt][k] = v;
            }
#pragma unroll
        for (int o = 4; o < 32; o <<= 1)
#pragma unroll
            for (int nt = 0; nt < 4; nt++)
#pragma unroll
                for (int k = 0; k < 2; k++)
                    cmx[nt][k] = fmaxf(cmx[nt][k], __shfl_xor_sync(0xffffffffu, cmx[nt][k], o));
        if (g == 0)
#pragma unroll
            for (int nt = 0; nt < 4; nt++)
#pragma unroll
                for (int k = 0; k < 2; k++)
                    s_a[wr * 128 + wc * 32 + nt * 8 + 2 * t4 + k] = cmx[nt][k];
        __syncthreads();
        if (tid < 128)
            s_fin[tid] = fmaxf(fmaxf(s_a[tid], s_a[128 + tid]), fmaxf(s_a[256 + tid], s_a[384 + tid]));
        __syncthreads();
        float csm[4][2];
#pragma unroll
        for (int nt = 0; nt < 4; nt++)
#pragma unroll
            for (int k = 0; k < 2; k++) {
                float fm = s_fin[wc * 32 + nt * 8 + 2 * t4 + k];
                float sa = 0.f;
#pragma unroll
                for (int mt = 0; mt < 4; mt++)
#pragma unroll
                    for (int h = 0; h < 2; h++) {
                        int row = n0 + wr * 64 + mt * 16 + h * 8 + g;
                        float x = (row < NPIX) ? acc[mt][nt][h * 2 + k] : -1e30f;
                        sa += fexp(x - fm);
                    }
                csm[nt][k] = sa;
            }
#pragma unroll
        for (int o = 4; o < 32; o <<= 1)
#pragma unroll
            for (int nt = 0; nt < 4; nt++)
#pragma unroll
                for (int k = 0; k < 2; k++)
                    csm[nt][k] += __shfl_xor_sync(0xffffffffu, csm[nt][k], o);
        __syncthreads();
        if (g == 0)
#pragma unroll
            for (int nt = 0; nt < 4; nt++)
#pragma unroll
                for (int k = 0; k < 2; k++)
                    s_a[wr * 128 + wc * 32 + nt * 8 + 2 * t4 + k] = csm[nt][k];
        __syncthreads();
        if (tid < 128) {
            int m = m0 + tid;
            if (m < NPIX) {
                int o = (blockIdx.y * 4 + b) * NPIX + m;
                g_cmax_p[o] = s_fin[tid];
                g_csum_p[o] = s_a[tid] + s_a[128 + tid] + s_a[256 + tid] + s_a[384 + tid];
            }
        }
    }
}

// ---------------- K5: merge row+col partials (fused) ----------------
__global__ void merge_kernel() {
    int idx = blockIdx.x * blockDim.x + threadIdx.x;
    int which = idx / (4 * NPIX);
    int sub = idx % (4 * NPIX);
    if (idx >= 8 * NPIX) return;
    if (which == 0) {
        float mx = -1e30f;
#pragma unroll
        for (int t = 0; t < NTIL; t++) mx = fmaxf(mx, g_rmax_p[t * 4 * NPIX + sub]);
        float s = 0.f;
#pragma unroll
        for (int t = 0; t < NTIL; t++)
            s += g_rsum_p[t * 4 * NPIX + sub] * fexp(g_rmax_p[t * 4 * NPIX + sub] - mx);
        g_hmax[sub] = mx;
        g_hs[sub]   = 1.f / (s + 1e-4f);
    } else {
        float mx = -1e30f;
#pragma unroll
        for (int t = 0; t < NTIL; t++) mx = fmaxf(mx, g_cmax_p[t * 4 * NPIX + sub]);
        float s = 0.f;
#pragma unroll
        for (int t = 0; t < NTIL; t++)
            s += g_csum_p[t * 4 * NPIX + sub] * fexp(g_cmax_p[t * 4 * NPIX + sub] - mx);
        g_vmax[sub] = mx;
        g_vs[sub]   = 1.f / (s + 1e-4f);
    }
}

// ---------------- K6: S[b,m] partial sums (half2 vectorized) ----------------
__global__ void spart_kernel() {
    int m2 = blockIdx.x * 256 + threadIdx.x;   // half2 index (2 m's per thread)
    int b = blockIdx.y, seg = blockIdx.z;
    if (m2 >= NPIX / 2) return;
    const __half2* Mh = (const __half2*)(g_M + (size_t)b * MSIZE);
    const __half2* Mv = (const __half2*)(g_M + (size_t)(4 + b) * MSIZE);
    int m = 2 * m2;
    float vm0 = g_vmax[b * NPIX + m], vm1 = g_vmax[b * NPIX + m + 1];
    float s0 = 0.f, s1 = 0.f;
    int n0 = seg * SEGN;
    const int RW = NPIX / 2;                   // half2 row stride
    for (int nb = 0; nb < SEGN; nb += 6) {
        float2 av[6], cv[6];
        float hm[6], hw[6];
#pragma unroll
        for (int j = 0; j < 6; j++) {
            int n = n0 + nb + j;
            av[j] = __half22float2(__ldcs(&Mv[(size_t)n * RW + m2]));
            cv[j] = __half22float2(__ldcs(&Mh[(size_t)n * RW + m2]));
            hm[j] = g_hmax[b * NPIX + n];
            hw[j] = g_hs[b * NPIX + n];
        }
#pragma unroll
        for (int j = 0; j < 6; j++) {
            float base0 = av[j].x + cv[j].x - hm[j];
            float base1 = av[j].y + cv[j].y - hm[j];
            s0 = fmaf(fexp(base0 - vm0), hw[j], s0);
            s1 = fmaf(fexp(base1 - vm1), hw[j], s1);
        }
    }
    float* Sp = &g_Spart[(seg * 4 + b) * NPIX + m];
    Sp[0] = s0;
    Sp[1] = s1;
}

// ---------------- K7a: parallel log partials ----------------
__global__ void fpart_kernel() {
    __shared__ float red[256];
    int blk = blockIdx.x;
    int t = threadIdx.x;
    int base = blk * (4 * NPIX / FBLK);
    float acc = 0.f;
    if (t < 240) {
        int idx = base + t;
        int b = idx / NPIX, m = idx % NPIX;
        float S = 0.f;
#pragma unroll
        for (int seg = 0; seg < SEG; seg++) S += g_Spart[(seg * 4 + b) * NPIX + m];
        acc = logf(S * g_vs[idx] + 1e-4f);
    }
    red[t] = acc; __syncthreads();
    for (int s = 128; s > 0; s >>= 1) { if (t < s) red[t] += red[t + s]; __syncthreads(); }
    if (t == 0) g_fpart[blk] = red[0];
}

// ---------------- K7b: deterministic final merge ----------------
__global__ void final_kernel(float* __restrict__ out) {
    __shared__ float red[64];
    int t = threadIdx.x;
    float acc = (t < FBLK) ? g_fpart[t] : 0.f;
    red[t] = acc; __syncthreads();
    for (int s = 32; s > 0; s >>= 1) { if (t < s) red[t] += red[t + s]; __syncthreads(); }
    if (t == 0) out[0] = red[0] * (1.f / (4.f * NPIX));
}

// ---------------- launch ----------------
extern "C" void kernel_launch(void* const* d_in, const int* in_sizes, int n_in,
                              void* d_out, int out_size) {
    const float* input_a = (const float*)d_in[0];
    const float* input_b = (const float*)d_in[1];
    const float* w1      = (const float*)d_in[2];
    const float* b1      = (const float*)d_in[3];
    const float* w2      = (const float*)d_in[4];
    const float* b2      = (const float*)d_in[5];
    const float* noise   = (const float*)d_in[6];
    const int*   u_roll  = (const int*)d_in[7];
    const int*   v_roll  = (const int*)d_in[8];
    const int*   swap    = (const int*)d_in[9];
    float* out = (float*)d_out;

    cudaFuncSetAttribute(gemm_hmma_kernel, cudaFuncAttributeMaxDynamicSharedMemorySize, GEMM_SMEM);
    cudaFuncSetAttribute(bwdconv1_kernel, cudaFuncAttributeMaxDynamicSharedMemorySize, BW_SMEM);

    fwd_sample_kernel<<<(16 * 3 * NPIX + 255) / 256, 256>>>(input_a, input_b, noise, swap, u_roll, v_roll);
    conv3_kernel<<<(16 * HIDC * NPIX + 255) / 256, 256>>>(w1, b1);
    bwdconv1_kernel<<<dim3((NPIX + PIXB - 1) / PIXB, 16), 256, BW_SMEM>>>(w2, b2, noise, swap, u_roll, v_roll);
    gemm_hmma_kernel<<<dim3(NTIL, NTIL, 8), 256, GEMM_SMEM>>>();
    merge_kernel<<<(8 * NPIX + 255) / 256, 256>>>();
    spart_kernel<<<dim3((NPIX / 2 + 255) / 256, 4, SEG), 256>>>();
    fpart_kernel<<<FBLK, 256>>>();
    final_kernel<<<1, 64>>>(out);
}

// round 14
// speedup vs baseline: 1.0177x; 1.0177x over previous
#include <cuda_runtime.h>
#include <cuda_fp16.h>
#include <stdint.h>

#define HW    60
#define NPIX  3600
#define HIDC  64
#define FEATC 128
#define MSIZE (3600LL*3600LL)
#define SEG   8
#define SEGN  450   /* 3600/8 */
#define NTIL  29    /* ceil(3600/128) */
#define PIXB  64    /* pixels per bwdconv1 block */
#define FBLK  60    /* final partial blocks */

// ---------------- static device scratch (no allocations allowed) ----------------
__device__ float g_xw[16*3*NPIX];            // forward-warped inputs
__device__ float g_h1[16L*NPIX*HIDC];        // conv3x3+relu, TRANSPOSED: [ib][pix][ch]
__device__ __half g_Fh[16L*NPIX*FEATC];      // features (fp16)
__device__ __half g_M [8L*3600*3600];        // [mat*4+b][n][m]  fp16 (~207MB)
__device__ float g_rmax_p[NTIL*4*NPIX], g_rsum_p[NTIL*4*NPIX];
__device__ float g_cmax_p[NTIL*4*NPIX], g_csum_p[NTIL*4*NPIX];
__device__ float g_hmax[4*NPIX], g_hs[4*NPIX];
__device__ float g_vmax[4*NPIX], g_vs[4*NPIX];
__device__ float g_Spart[SEG*4*NPIX];
__device__ float g_fpart[FBLK];

// Fast exp on the FMA pipe (no MUFU). rel err ~2e-5.
__device__ __forceinline__ float fexp(float x) {
    float t = x * 1.4426950408889634f;
    t = fmaxf(t, -125.0f);
    float r = floorf(t);
    float f = t - r;
    float p = 1.5403530e-4f;
    p = fmaf(p, f, 1.3333558e-3f);
    p = fmaf(p, f, 9.6181291e-3f);
    p = fmaf(p, f, 5.5504109e-2f);
    p = fmaf(p, f, 2.4022651e-1f);
    p = fmaf(p, f, 6.9314718e-1f);
    p = fmaf(p, f, 1.0f);
    int ei = (int)r;
    return __int_as_float((ei + 127) << 23) * p;
}

__device__ __forceinline__ void compute_theta(const float* __restrict__ noise, int swp, int ib,
                                              float* TA, float* TB) {
    const float* nz = noise + ib * 9;
    float a  = 1.f + 0.05f * nz[0], b = 0.05f * nz[1], c = 0.05f * nz[2];
    float d  = 0.05f * nz[3], e = 1.f + 0.05f * nz[4], f = 0.05f * nz[5];
    float id = 1.f / (a * e - b * d);
    float fwd[6] = {a, b, c, d, e, f};
    float bwd[6] = { e * id, -b * id, (b * f - c * e) * id,
                    -d * id,  a * id, (c * d - a * f) * id};
    bool s = (swp == 1);
#pragma unroll
    for (int k = 0; k < 6; k++) {
        if (TA) TA[k] = s ? bwd[k] : fwd[k];
        if (TB) TB[k] = s ? fwd[k] : bwd[k];
    }
}

// ---------------- K1: forward grid_sample ----------------
__global__ void fwd_sample_kernel(const float* __restrict__ inA, const float* __restrict__ inB,
                                  const float* __restrict__ noise, const int* __restrict__ swap,
                                  const int* __restrict__ u_roll, const int* __restrict__ v_roll) {
    int idx = blockIdx.x * blockDim.x + threadIdx.x;
    if (idx >= 16 * 3 * NPIX) return;
    int p  = idx % NPIX;
    int c  = (idx / NPIX) % 3;
    int ib = idx / (3 * NPIX);
    int i  = ib >> 2, b = ib & 3;
    float T[6];
    compute_theta(noise, swap[i], ib, T, nullptr);
    int r = p / HW, cc = p % HW;
    float xn = (2 * cc + 1) * (1.f / HW) - 1.f;
    float yn = (2 * r  + 1) * (1.f / HW) - 1.f;
    float gx = T[0] * xn + T[1] * yn + T[2];
    float gy = T[3] * xn + T[4] * yn + T[5];
    float x = (gx + 1.f) * (HW * 0.5f) - 0.5f;
    float y = (gy + 1.f) * (HW * 0.5f) - 0.5f;
    float x0f = floorf(x), y0f = floorf(y);
    int x0 = (int)x0f, y0 = (int)y0f;
    float wx1 = x - x0f, wx0 = 1.f - wx1;
    float wy1 = y - y0f, wy0 = 1.f - wy1;
    const float* src = ((i & 1) == 0) ? inA : inB;
    src += (b * 3 + c) * NPIX;
    int u = u_roll[ib], v = v_roll[ib];
    float acc = 0.f;
#pragma unroll
    for (int ky = 0; ky < 2; ky++) {
        int iy = y0 + ky;
        if (iy < 0 || iy >= HW) continue;
        int ry = iy + u; if (ry >= HW) ry -= HW;
        float wy = ky ? wy1 : wy0;
#pragma unroll
        for (int kx = 0; kx < 2; kx++) {
            int ix = x0 + kx;
            if (ix < 0 || ix >= HW) continue;
            int rx = ix + v; if (rx >= HW) rx -= HW;
            acc += wy * (kx ? wx1 : wx0) * src[ry * HW + rx];
        }
    }
    g_xw[ib * 3 * NPIX + c * NPIX + p] = acc;
}

// ---------------- K2: conv3x3 (3->64) + relu, transposed out ----------------
__global__ void conv3_kernel(const float* __restrict__ w1, const float* __restrict__ b1) {
    int idx = blockIdx.x * blockDim.x + threadIdx.x;
    if (idx >= 16 * HIDC * NPIX) return;
    int p  = idx % NPIX;
    int oc = (idx / NPIX) % HIDC;
    int ib = idx / (NPIX * HIDC);
    int r = p / HW, c = p % HW;
    const float* xin = g_xw + ib * 3 * NPIX;
    const float* wk  = w1 + oc * 27;
    float acc = b1[oc];
#pragma unroll
    for (int ci = 0; ci < 3; ci++)
#pragma unroll
        for (int dy = -1; dy <= 1; dy++) {
            int rr = r + dy;
            if (rr < 0 || rr >= HW) continue;
#pragma unroll
            for (int dx = -1; dx <= 1; dx++) {
                int c2 = c + dx;
                if (c2 < 0 || c2 >= HW) continue;
                acc += wk[ci * 9 + (dy + 1) * 3 + (dx + 1)] * xin[ci * NPIX + rr * HW + c2];
            }
        }
    g_h1[((size_t)ib * NPIX + p) * HIDC + oc] = fmaxf(acc, 0.f);
}

// ---------------- K3: fused backward grid_sample + conv1x1 (dynamic smem) ----------------
#define BW_W2S   0
#define BW_HS    (FEATC * 65)
#define BW_WTS   (BW_HS + PIXB * 68)
#define BW_WSS   (BW_WTS + PIXB * 4)
#define BW_PPS   (BW_WSS + PIXB)
#define BW_SMEM  ((BW_PPS + PIXB * 4) * 4)
__global__ __launch_bounds__(256) void bwdconv1_kernel(
        const float* __restrict__ w2, const float* __restrict__ b2,
        const float* __restrict__ noise, const int* __restrict__ swap,
        const int* __restrict__ u_roll, const int* __restrict__ v_roll) {
    extern __shared__ float smf[];
    float* w2s = smf + BW_W2S;
    float* Hs  = smf + BW_HS;
    float* wts = smf + BW_WTS;
    float* wss = smf + BW_WSS;
    int*   pps = (int*)(smf + BW_PPS);

    int ib = blockIdx.y;
    int p0 = blockIdx.x * PIXB;
    int tid = threadIdx.x;

    for (int i = tid; i < FEATC * HIDC; i += 256)
        w2s[(i >> 6) * 65 + (i & 63)] = w2[i];

    if (tid < PIXB) {
        int gp = p0 + tid;
        float T[6];
        compute_theta(noise, swap[ib >> 2], ib, nullptr, T);
        int u = u_roll[ib], v = v_roll[ib];
        int n = (gp < NPIX) ? gp : NPIX - 1;
        int r = n / HW, c = n % HW;
        int rr = r - u; if (rr < 0) rr += HW;
        int cc = c - v; if (cc < 0) cc += HW;
        float xn = (2 * cc + 1) * (1.f / HW) - 1.f;
        float yn = (2 * rr + 1) * (1.f / HW) - 1.f;
        float gx = T[0] * xn + T[1] * yn + T[2];
        float gy = T[3] * xn + T[4] * yn + T[5];
        float x = (gx + 1.f) * (HW * 0.5f) - 0.5f;
        float y = (gy + 1.f) * (HW * 0.5f) - 0.5f;
        float x0f = floorf(x), y0f = floorf(y);
        int x0 = (int)x0f, y0 = (int)y0f;
        float wx1 = x - x0f, wx0 = 1.f - wx1;
        float wy1 = y - y0f, wy0 = 1.f - wy1;
        float ws = 0.f;
#pragma unroll
        for (int k = 0; k < 4; k++) {
            int iy = y0 + (k >> 1), ix = x0 + (k & 1);
            bool ok = (iy >= 0 && iy < HW && ix >= 0 && ix < HW) && (gp < NPIX);
            pps[tid * 4 + k] = ok ? (iy * HW + ix) : -1;
            float w = ((k >> 1) ? wy1 : wy0) * ((k & 1) ? wx1 : wx0);
            wts[tid * 4 + k] = w;
            if (ok) ws += w;
        }
        wss[tid] = ws;
    }
    __syncthreads();

    const float* hb = g_h1 + (size_t)ib * NPIX * HIDC;
#pragma unroll
    for (int e = 0; e < 16; e++) {
        int idx = tid + e * 256;
        int ch = idx & 63, pix = idx >> 6;
        float a = 0.f;
#pragma unroll
        for (int k = 0; k < 4; k++) {
            int q = pps[pix * 4 + k];
            if (q >= 0) a += wts[pix * 4 + k] * hb[(size_t)q * HIDC + ch];
        }
        Hs[pix * 68 + ch] = a;
    }
    __syncthreads();

    int d = tid & 127;
    float wreg[HIDC];
#pragma unroll
    for (int h = 0; h < HIDC; h++) wreg[h] = w2s[d * 65 + h];
    float bd = b2[d];

#pragma unroll 4
    for (int pass = 0; pass < 32; pass++) {
        int pix = pass * 2 + (tid >> 7);
        int gp = p0 + pix;
        float acc = wss[pix] * bd;
        const float4* hv = (const float4*)&Hs[pix * 68];
#pragma unroll
        for (int h4 = 0; h4 < 16; h4++) {
            float4 hvv = hv[h4];
            acc = fmaf(wreg[h4 * 4 + 0], hvv.x, acc);
            acc = fmaf(wreg[h4 * 4 + 1], hvv.y, acc);
            acc = fmaf(wreg[h4 * 4 + 2], hvv.z, acc);
            acc = fmaf(wreg[h4 * 4 + 3], hvv.w, acc);
        }
        if (gp < NPIX)
            g_Fh[((size_t)ib * NPIX + gp) * FEATC + d] = __float2half_rn(acc);
    }
}

// ---------------- K4: single-term fp16 HMMA GEMM, 128x128, fp16 C (R11 form) ----------------
#define SA_HI 0
#define SBH_OFF 32768
#define GEMM_SMEM 65536
__device__ __forceinline__ uint32_t sw_off(int r, int c16) {
    return (uint32_t)(r * 256 + ((((c16 ^ r) & 7)) | (c16 & 8)) * 16);
}
__device__ __forceinline__ uint32_t smem_u32(const void* p) {
    uint32_t a;
    asm("{ .reg .u64 t; cvta.to.shared.u64 t, %1; cvt.u32.u64 %0, t; }" : "=r"(a) : "l"(p));
    return a;
}
#define LDSM_X4(R0, R1, R2, R3, addr)                                             \
    asm volatile("ldmatrix.sync.aligned.m8n8.x4.shared.b16 {%0,%1,%2,%3}, [%4];"  \
                 : "=r"(R0), "=r"(R1), "=r"(R2), "=r"(R3) : "r"(addr))
#define HMMA16816(D, A0, A1, A2, A3, B0, B1)                                      \
    asm volatile("mma.sync.aligned.m16n8k16.row.col.f32.f16.f16.f32 "             \
                 "{%0,%1,%2,%3}, {%4,%5,%6,%7}, {%8,%9}, {%0,%1,%2,%3};\n"        \
                 : "+f"(D[0]), "+f"(D[1]), "+f"(D[2]), "+f"(D[3])                 \
                 : "r"(A0), "r"(A1), "r"(A2), "r"(A3), "r"(B0), "r"(B1))

__global__ __launch_bounds__(256, 2) void gemm_hmma_kernel() {
    extern __shared__ char smem[];
    uint32_t sb = smem_u32(smem);
    int z = blockIdx.z;
    int mat = z >> 2, b = z & 3;
    size_t baseA = (size_t)((mat * 2)     * 4 + b) * NPIX * FEATC;
    size_t baseB = (size_t)((mat * 2 + 1) * 4 + b) * NPIX * FEATC;
    __half* C = g_M + (size_t)z * MSIZE;
    int n0 = blockIdx.y * 128, m0 = blockIdx.x * 128;
    int tid = threadIdx.x;
    int wid = tid >> 5, lane = tid & 31;
    int wr = wid >> 2, wc = wid & 3;

    // ---- copy A, B (2 x 2048 uint4) ----
    {
        const uint4* srcA = (const uint4*)(g_Fh + baseA);
        const uint4* srcB = (const uint4*)(g_Fh + baseB);
#pragma unroll
        for (int i = 0; i < 8; i++) {
            int slot = tid + i * 256;
            int c16 = slot & 15, row = slot >> 4;
            int gr = n0 + row, gm = m0 + row;
            uint4 va = make_uint4(0, 0, 0, 0), vb = va;
            if (gr < NPIX) va = srcA[gr * 16 + c16];
            if (gm < NPIX) vb = srcB[gm * 16 + c16];
            uint32_t o = sw_off(row, c16);
            *(uint4*)(smem + SA_HI  + o) = va;
            *(uint4*)(smem + SBH_OFF + o) = vb;
        }
    }
    __syncthreads();

    float acc[4][4][4];
#pragma unroll
    for (int u = 0; u < 4; u++)
#pragma unroll
        for (int v = 0; v < 4; v++)
#pragma unroll
            for (int r = 0; r < 4; r++) acc[u][v][r] = 0.f;

    int a_row_l = ((lane >> 3) & 1) * 8 + (lane & 7);
    int a_c16_l = (lane >> 4);
    int b_row_l = ((lane >> 4) * 8) + (lane & 7);
    int b_c16_l = ((lane >> 3) & 1);

#pragma unroll
    for (int kt = 0; kt < 8; kt++) {
        uint32_t ah[4][4], bh[4][2];
#pragma unroll
        for (int mt = 0; mt < 4; mt++) {
            uint32_t off = sw_off(wr * 64 + mt * 16 + a_row_l, 2 * kt + a_c16_l);
            LDSM_X4(ah[mt][0], ah[mt][1], ah[mt][2], ah[mt][3], sb + SA_HI + off);
        }
#pragma unroll
        for (int np = 0; np < 2; np++) {
            uint32_t off = sw_off(wc * 32 + np * 16 + b_row_l, 2 * kt + b_c16_l);
            LDSM_X4(bh[np * 2][0], bh[np * 2][1], bh[np * 2 + 1][0], bh[np * 2 + 1][1], sb + SBH_OFF + off);
        }
#pragma unroll
        for (int mt = 0; mt < 4; mt++)
#pragma unroll
            for (int nt = 0; nt < 4; nt++)
                HMMA16816(acc[mt][nt], ah[mt][0], ah[mt][1], ah[mt][2], ah[mt][3], bh[nt][0], bh[nt][1]);
    }

    // ---- store C (fp16, default policy) ----
    int g = lane >> 2, t4 = lane & 3;
#pragma unroll
    for (int mt = 0; mt < 4; mt++) {
        int r0 = n0 + wr * 64 + mt * 16 + g;
#pragma unroll
        for (int nt = 0; nt < 4; nt++) {
            int col = m0 + wc * 32 + nt * 8 + 2 * t4;
            if (col < NPIX) {
                if (r0 < NPIX)
                    *(__half2*)&C[(size_t)r0 * NPIX + col] = __floats2half2_rn(acc[mt][nt][0], acc[mt][nt][1]);
                if (r0 + 8 < NPIX)
                    *(__half2*)&C[(size_t)(r0 + 8) * NPIX + col] = __floats2half2_rn(acc[mt][nt][2], acc[mt][nt][3]);
            }
        }
    }

    // ---- fused per-tile softmax stats ----
    __syncthreads();
    float* s_a   = (float*)smem;
    float* s_fin = (float*)smem + 512;

    if (mat == 0) {
        float rmx[4][2];
#pragma unroll
        for (int mt = 0; mt < 4; mt++)
#pragma unroll
            for (int h = 0; h < 2; h++) {
                float v = -1e30f;
#pragma unroll
                for (int nt = 0; nt < 4; nt++)
#pragma unroll
                    for (int k = 0; k < 2; k++) {
                        int col = m0 + wc * 32 + nt * 8 + 2 * t4 + k;
                        float x = (col < NPIX) ? acc[mt][nt][h * 2 + k] : -1e30f;
                        v = fmaxf(v, x);
                    }
                rmx[mt][h] = v;
            }
#pragma unroll
        for (int o = 1; o < 4; o <<= 1)
#pragma unroll
            for (int mt = 0; mt < 4; mt++)
#pragma unroll
                for (int h = 0; h < 2; h++)
                    rmx[mt][h] = fmaxf(rmx[mt][h], __shfl_xor_sync(0xffffffffu, rmx[mt][h], o));
        if (t4 == 0)
#pragma unroll
            for (int mt = 0; mt < 4; mt++)
#pragma unroll
                for (int h = 0; h < 2; h++)
                    s_a[wc * 128 + wr * 64 + mt * 16 + h * 8 + g] = rmx[mt][h];
        __syncthreads();
        if (tid < 128)
            s_fin[tid] = fmaxf(fmaxf(s_a[tid], s_a[128 + tid]), fmaxf(s_a[256 + tid], s_a[384 + tid]));
        __syncthreads();
        float rsm[4][2];
#pragma unroll
        for (int mt = 0; mt < 4; mt++)
#pragma unroll
            for (int h = 0; h < 2; h++) {
                float fm = s_fin[wr * 64 + mt * 16 + h * 8 + g];
                float sa = 0.f;
#pragma unroll
                for (int nt = 0; nt < 4; nt++)
#pragma unroll
                    for (int k = 0; k < 2; k++) {
                        int col = m0 + wc * 32 + nt * 8 + 2 * t4 + k;
                        float x = (col < NPIX) ? acc[mt][nt][h * 2 + k] : -1e30f;
                        sa += fexp(x - fm);
                    }
                rsm[mt][h] = sa;
            }
#pragma unroll
        for (int o = 1; o < 4; o <<= 1)
#pragma unroll
            for (int mt = 0; mt < 4; mt++)
#pragma unroll
                for (int h = 0; h < 2; h++)
                    rsm[mt][h] += __shfl_xor_sync(0xffffffffu, rsm[mt][h], o);
        __syncthreads();
        if (t4 == 0)
#pragma unroll
            for (int mt = 0; mt < 4; mt++)
#pragma unroll
                for (int h = 0; h < 2; h++)
                    s_a[wc * 128 + wr * 64 + mt * 16 + h * 8 + g] = rsm[mt][h];
        __syncthreads();
        if (tid < 128) {
            int n = n0 + tid;
            if (n < NPIX) {
                int o = (blockIdx.x * 4 + b) * NPIX + n;
                g_rmax_p[o] = s_fin[tid];
                g_rsum_p[o] = s_a[tid] + s_a[128 + tid] + s_a[256 + tid] + s_a[384 + tid];
            }
        }
    } else {
        float cmx[4][2];
#pragma unroll
        for (int nt = 0; nt < 4; nt++)
#pragma unroll
            for (int k = 0; k < 2; k++) {
                float v = -1e30f;
#pragma unroll
                for (int mt = 0; mt < 4; mt++)
#pragma unroll
                    for (int h = 0; h < 2; h++) {
                        int row = n0 + wr * 64 + mt * 16 + h * 8 + g;
                        float x = (row < NPIX) ? acc[mt][nt][h * 2 + k] : -1e30f;
                        v = fmaxf(v, x);
                    }
                cmx[nt][k] = v;
            }
#pragma unroll
        for (int o = 4; o < 32; o <<= 1)
#pragma unroll
            for (int nt = 0; nt < 4; nt++)
#pragma unroll
                for (int k = 0; k < 2; k++)
                    cmx[nt][k] = fmaxf(cmx[nt][k], __shfl_xor_sync(0xffffffffu, cmx[nt][k], o));
        if (g == 0)
#pragma unroll
            for (int nt = 0; nt < 4; nt++)
#pragma unroll
                for (int k = 0; k < 2; k++)
                    s_a[wr * 128 + wc * 32 + nt * 8 + 2 * t4 + k] = cmx[nt][k];
        __syncthreads();
        if (tid < 128)
            s_fin[tid] = fmaxf(fmaxf(s_a[tid], s_a[128 + tid]), fmaxf(s_a[256 + tid], s_a[384 + tid]));
        __syncthreads();
        float csm[4][2];
#pragma unroll
        for (int nt = 0; nt < 4; nt++)
#pragma unroll
            for (int k = 0; k < 2; k++) {
                float fm = s_fin[wc * 32 + nt * 8 + 2 * t4 + k];
                float sa = 0.f;
#pragma unroll
                for (int mt = 0; mt < 4; mt++)
#pragma unroll
                    for (int h = 0; h < 2; h++) {
                        int row = n0 + wr * 64 + mt * 16 + h * 8 + g;
                        float x = (row < NPIX) ? acc[mt][nt][h * 2 + k] : -1e30f;
                        sa += fexp(x - fm);
                    }
                csm[nt][k] = sa;
            }
#pragma unroll
        for (int o = 4; o < 32; o <<= 1)
#pragma unroll
            for (int nt = 0; nt < 4; nt++)
#pragma unroll
                for (int k = 0; k < 2; k++)
                    csm[nt][k] += __shfl_xor_sync(0xffffffffu, csm[nt][k], o);
        __syncthreads();
        if (g == 0)
#pragma unroll
            for (int nt = 0; nt < 4; nt++)
#pragma unroll
                for (int k = 0; k < 2; k++)
                    s_a[wr * 128 + wc * 32 + nt * 8 + 2 * t4 + k] = csm[nt][k];
        __syncthreads();
        if (tid < 128) {
            int m = m0 + tid;
            if (m < NPIX) {
                int o = (blockIdx.y * 4 + b) * NPIX + m;
                g_cmax_p[o] = s_fin[tid];
                g_csum_p[o] = s_a[tid] + s_a[128 + tid] + s_a[256 + tid] + s_a[384 + tid];
            }
        }
    }
}

// ---------------- K5: merge row+col partials (fused) ----------------
__global__ void merge_kernel() {
    int idx = blockIdx.x * blockDim.x + threadIdx.x;
    int which = idx / (4 * NPIX);
    int sub = idx % (4 * NPIX);
    if (idx >= 8 * NPIX) return;
    if (which == 0) {
        float mx = -1e30f;
#pragma unroll
        for (int t = 0; t < NTIL; t++) mx = fmaxf(mx, g_rmax_p[t * 4 * NPIX + sub]);
        float s = 0.f;
#pragma unroll
        for (int t = 0; t < NTIL; t++)
            s += g_rsum_p[t * 4 * NPIX + sub] * fexp(g_rmax_p[t * 4 * NPIX + sub] - mx);
        g_hmax[sub] = mx;
        g_hs[sub]   = 1.f / (s + 1e-4f);
    } else {
        float mx = -1e30f;
#pragma unroll
        for (int t = 0; t < NTIL; t++) mx = fmaxf(mx, g_cmax_p[t * 4 * NPIX + sub]);
        float s = 0.f;
#pragma unroll
        for (int t = 0; t < NTIL; t++)
            s += g_csum_p[t * 4 * NPIX + sub] * fexp(g_cmax_p[t * 4 * NPIX + sub] - mx);
        g_vmax[sub] = mx;
        g_vs[sub]   = 1.f / (s + 1e-4f);
    }
}

// ---------------- K6: S[b,m] partial sums (half2 vectorized, default-policy loads) ----------------
__global__ void spart_kernel() {
    int m2 = blockIdx.x * 256 + threadIdx.x;   // half2 index (2 m's per thread)
    int b = blockIdx.y, seg = blockIdx.z;
    if (m2 >= NPIX / 2) return;
    const __half2* Mh = (const __half2*)(g_M + (size_t)b * MSIZE);
    const __half2* Mv = (const __half2*)(g_M + (size_t)(4 + b) * MSIZE);
    int m = 2 * m2;
    float vm0 = g_vmax[b * NPIX + m], vm1 = g_vmax[b * NPIX + m + 1];
    float s0 = 0.f, s1 = 0.f;
    int n0 = seg * SEGN;
    const int RW = NPIX / 2;                   // half2 row stride
    for (int nb = 0; nb < SEGN; nb += 6) {
        float2 av[6], cv[6];
        float hm[6], hw[6];
#pragma unroll
        for (int j = 0; j < 6; j++) {
            int n = n0 + nb + j;
            av[j] = __half22float2(Mv[(size_t)n * RW + m2]);
            cv[j] = __half22float2(Mh[(size_t)n * RW + m2]);
            hm[j] = g_hmax[b * NPIX + n];
            hw[j] = g_hs[b * NPIX + n];
        }
#pragma unroll
        for (int j = 0; j < 6; j++) {
            float base0 = av[j].x + cv[j].x - hm[j];
            float base1 = av[j].y + cv[j].y - hm[j];
            s0 = fmaf(fexp(base0 - vm0), hw[j], s0);
            s1 = fmaf(fexp(base1 - vm1), hw[j], s1);
        }
    }
    float* Sp = &g_Spart[(seg * 4 + b) * NPIX + m];
    Sp[0] = s0;
    Sp[1] = s1;
}

// ---------------- K7a: parallel log partials ----------------
__global__ void fpart_kernel() {
    __shared__ float red[256];
    int blk = blockIdx.x;
    int t = threadIdx.x;
    int base = blk * (4 * NPIX / FBLK);
    float acc = 0.f;
    if (t < 240) {
        int idx = base + t;
        int b = idx / NPIX, m = idx % NPIX;
        float S = 0.f;
#pragma unroll
        for (int seg = 0; seg < SEG; seg++) S += g_Spart[(seg * 4 + b) * NPIX + m];
        acc = logf(S * g_vs[idx] + 1e-4f);
    }
    red[t] = acc; __syncthreads();
    for (int s = 128; s > 0; s >>= 1) { if (t < s) red[t] += red[t + s]; __syncthreads(); }
    if (t == 0) g_fpart[blk] = red[0];
}

// ---------------- K7b: deterministic final merge ----------------
__global__ void final_kernel(float* __restrict__ out) {
    __shared__ float red[64];
    int t = threadIdx.x;
    float acc = (t < FBLK) ? g_fpart[t] : 0.f;
    red[t] = acc; __syncthreads();
    for (int s = 32; s > 0; s >>= 1) { if (t < s) red[t] += red[t + s]; __syncthreads(); }
    if (t == 0) out[0] = red[0] * (1.f / (4.f * NPIX));
}

// ---------------- launch ----------------
extern "C" void kernel_launch(void* const* d_in, const int* in_sizes, int n_in,
                              void* d_out, int out_size) {
    const float* input_a = (const float*)d_in[0];
    const float* input_b = (const float*)d_in[1];
    const float* w1      = (const float*)d_in[2];
    const float* b1      = (const float*)d_in[3];
    const float* w2      = (const float*)d_in[4];
    const float* b2      = (const float*)d_in[5];
    const float* noise   = (const float*)d_in[6];
    const int*   u_roll  = (const int*)d_in[7];
    const int*   v_roll  = (const int*)d_in[8];
    const int*   swap    = (const int*)d_in[9];
    float* out = (float*)d_out;

    cudaFuncSetAttribute(gemm_hmma_kernel, cudaFuncAttributeMaxDynamicSharedMemorySize, GEMM_SMEM);
    cudaFuncSetAttribute(bwdconv1_kernel, cudaFuncAttributeMaxDynamicSharedMemorySize, BW_SMEM);

    fwd_sample_kernel<<<(16 * 3 * NPIX + 255) / 256, 256>>>(input_a, input_b, noise, swap, u_roll, v_roll);
    conv3_kernel<<<(16 * HIDC * NPIX + 255) / 256, 256>>>(w1, b1);
    bwdconv1_kernel<<<dim3((NPIX + PIXB - 1) / PIXB, 16), 256, BW_SMEM>>>(w2, b2, noise, swap, u_roll, v_roll);
    gemm_hmma_kernel<<<dim3(NTIL, NTIL, 8), 256, GEMM_SMEM>>>();
    merge_kernel<<<(8 * NPIX + 255) / 256, 256>>>();
    spart_kernel<<<dim3((NPIX / 2 + 255) / 256, 4, SEG), 256>>>();
    fpart_kernel<<<FBLK, 256>>>();
    final_kernel<<<1, 64>>>(out);
}

// round 15
// speedup vs baseline: 1.1058x; 1.0865x over previous
#include <cuda_runtime.h>
#include <cuda_fp16.h>
#include <stdint.h>

#define HW    60
#define NPIX  3600
#define HIDC  64
#define FEATC 128
#define MSIZE (3600LL*3600LL)
#define SEG   8
#define SEGN  450   /* 3600/8 */
#define NTIL  29    /* ceil(3600/128) */
#define PIXB  64    /* pixels per bwdconv1 block */
#define FBLK  60    /* final partial blocks */

// ---------------- static device scratch (no allocations allowed) ----------------
__device__ float g_xw[16*3*NPIX];            // forward-warped inputs
__device__ float g_h1[16L*NPIX*HIDC];        // conv3x3+relu, TRANSPOSED: [ib][pix][ch]
__device__ __half g_Fh[16L*NPIX*FEATC];      // features (fp16)
__device__ __half g_M [8L*3600*3600];        // [mat*4+b][n][m]  fp16 (~207MB)
__device__ float g_rmax_p[NTIL*4*NPIX], g_rsum_p[NTIL*4*NPIX];
__device__ float g_cmax_p[NTIL*4*NPIX], g_csum_p[NTIL*4*NPIX];
__device__ float g_hmax[4*NPIX], g_hs[4*NPIX];
__device__ float g_vmax[4*NPIX], g_vs[4*NPIX];
__device__ float g_Spart[SEG*4*NPIX];
__device__ float g_fpart[FBLK];

// Fast exp on the FMA pipe (no MUFU). rel err ~2e-5.
__device__ __forceinline__ float fexp(float x) {
    float t = x * 1.4426950408889634f;
    t = fmaxf(t, -125.0f);
    float r = floorf(t);
    float f = t - r;
    float p = 1.5403530e-4f;
    p = fmaf(p, f, 1.3333558e-3f);
    p = fmaf(p, f, 9.6181291e-3f);
    p = fmaf(p, f, 5.5504109e-2f);
    p = fmaf(p, f, 2.4022651e-1f);
    p = fmaf(p, f, 6.9314718e-1f);
    p = fmaf(p, f, 1.0f);
    int ei = (int)r;
    return __int_as_float((ei + 127) << 23) * p;
}

__device__ __forceinline__ void compute_theta(const float* __restrict__ noise, int swp, int ib,
                                              float* TA, float* TB) {
    const float* nz = noise + ib * 9;
    float a  = 1.f + 0.05f * nz[0], b = 0.05f * nz[1], c = 0.05f * nz[2];
    float d  = 0.05f * nz[3], e = 1.f + 0.05f * nz[4], f = 0.05f * nz[5];
    float id = 1.f / (a * e - b * d);
    float fwd[6] = {a, b, c, d, e, f};
    float bwd[6] = { e * id, -b * id, (b * f - c * e) * id,
                    -d * id,  a * id, (c * d - a * f) * id};
    bool s = (swp == 1);
#pragma unroll
    for (int k = 0; k < 6; k++) {
        if (TA) TA[k] = s ? bwd[k] : fwd[k];
        if (TB) TB[k] = s ? fwd[k] : bwd[k];
    }
}

// ---------------- K1: forward grid_sample ----------------
__global__ void fwd_sample_kernel(const float* __restrict__ inA, const float* __restrict__ inB,
                                  const float* __restrict__ noise, const int* __restrict__ swap,
                                  const int* __restrict__ u_roll, const int* __restrict__ v_roll) {
    int idx = blockIdx.x * blockDim.x + threadIdx.x;
    if (idx >= 16 * 3 * NPIX) return;
    int p  = idx % NPIX;
    int c  = (idx / NPIX) % 3;
    int ib = idx / (3 * NPIX);
    int i  = ib >> 2, b = ib & 3;
    float T[6];
    compute_theta(noise, swap[i], ib, T, nullptr);
    int r = p / HW, cc = p % HW;
    float xn = (2 * cc + 1) * (1.f / HW) - 1.f;
    float yn = (2 * r  + 1) * (1.f / HW) - 1.f;
    float gx = T[0] * xn + T[1] * yn + T[2];
    float gy = T[3] * xn + T[4] * yn + T[5];
    float x = (gx + 1.f) * (HW * 0.5f) - 0.5f;
    float y = (gy + 1.f) * (HW * 0.5f) - 0.5f;
    float x0f = floorf(x), y0f = floorf(y);
    int x0 = (int)x0f, y0 = (int)y0f;
    float wx1 = x - x0f, wx0 = 1.f - wx1;
    float wy1 = y - y0f, wy0 = 1.f - wy1;
    const float* src = ((i & 1) == 0) ? inA : inB;
    src += (b * 3 + c) * NPIX;
    int u = u_roll[ib], v = v_roll[ib];
    float acc = 0.f;
#pragma unroll
    for (int ky = 0; ky < 2; ky++) {
        int iy = y0 + ky;
        if (iy < 0 || iy >= HW) continue;
        int ry = iy + u; if (ry >= HW) ry -= HW;
        float wy = ky ? wy1 : wy0;
#pragma unroll
        for (int kx = 0; kx < 2; kx++) {
            int ix = x0 + kx;
            if (ix < 0 || ix >= HW) continue;
            int rx = ix + v; if (rx >= HW) rx -= HW;
            acc += wy * (kx ? wx1 : wx0) * src[ry * HW + rx];
        }
    }
    g_xw[ib * 3 * NPIX + c * NPIX + p] = acc;
}

// ---------------- K2: conv3x3 (3->64) + relu, oc-fast mapping (coalesced stores) ----------------
__global__ void conv3_kernel(const float* __restrict__ w1, const float* __restrict__ b1) {
    int idx = blockIdx.x * blockDim.x + threadIdx.x;
    if (idx >= 16 * HIDC * NPIX) return;
    int oc = idx & (HIDC - 1);                 // fast dim: output channel
    int pp = idx >> 6;                         // ib*NPIX + p
    int p  = pp % NPIX;
    int ib = pp / NPIX;
    int r = p / HW, c = p % HW;
    const float* xin = g_xw + ib * 3 * NPIX;   // warp-uniform reads (broadcast)
    const float* wk  = w1 + oc * 27;
    float acc = b1[oc];
#pragma unroll
    for (int ci = 0; ci < 3; ci++)
#pragma unroll
        for (int dy = -1; dy <= 1; dy++) {
            int rr = r + dy;
            if (rr < 0 || rr >= HW) continue;
#pragma unroll
            for (int dx = -1; dx <= 1; dx++) {
                int c2 = c + dx;
                if (c2 < 0 || c2 >= HW) continue;
                acc += wk[ci * 9 + (dy + 1) * 3 + (dx + 1)] * xin[ci * NPIX + rr * HW + c2];
            }
        }
    g_h1[idx] = fmaxf(acc, 0.f);               // coalesced store
}

// ---------------- K3: fused backward grid_sample + conv1x1 (dynamic smem) ----------------
#define BW_W2S   0
#define BW_HS    (FEATC * 65)
#define BW_WTS   (BW_HS + PIXB * 68)
#define BW_WSS   (BW_WTS + PIXB * 4)
#define BW_PPS   (BW_WSS + PIXB)
#define BW_SMEM  ((BW_PPS + PIXB * 4) * 4)
__global__ __launch_bounds__(256) void bwdconv1_kernel(
        const float* __restrict__ w2, const float* __restrict__ b2,
        const float* __restrict__ noise, const int* __restrict__ swap,
        const int* __restrict__ u_roll, const int* __restrict__ v_roll) {
    extern __shared__ float smf[];
    float* w2s = smf + BW_W2S;
    float* Hs  = smf + BW_HS;
    float* wts = smf + BW_WTS;
    float* wss = smf + BW_WSS;
    int*   pps = (int*)(smf + BW_PPS);

    int ib = blockIdx.y;
    int p0 = blockIdx.x * PIXB;
    int tid = threadIdx.x;

    for (int i = tid; i < FEATC * HIDC; i += 256)
        w2s[(i >> 6) * 65 + (i & 63)] = w2[i];

    if (tid < PIXB) {
        int gp = p0 + tid;
        float T[6];
        compute_theta(noise, swap[ib >> 2], ib, nullptr, T);
        int u = u_roll[ib], v = v_roll[ib];
        int n = (gp < NPIX) ? gp : NPIX - 1;
        int r = n / HW, c = n % HW;
        int rr = r - u; if (rr < 0) rr += HW;
        int cc = c - v; if (cc < 0) cc += HW;
        float xn = (2 * cc + 1) * (1.f / HW) - 1.f;
        float yn = (2 * rr + 1) * (1.f / HW) - 1.f;
        float gx = T[0] * xn + T[1] * yn + T[2];
        float gy = T[3] * xn + T[4] * yn + T[5];
        float x = (gx + 1.f) * (HW * 0.5f) - 0.5f;
        float y = (gy + 1.f) * (HW * 0.5f) - 0.5f;
        float x0f = floorf(x), y0f = floorf(y);
        int x0 = (int)x0f, y0 = (int)y0f;
        float wx1 = x - x0f, wx0 = 1.f - wx1;
        float wy1 = y - y0f, wy0 = 1.f - wy1;
        float ws = 0.f;
#pragma unroll
        for (int k = 0; k < 4; k++) {
            int iy = y0 + (k >> 1), ix = x0 + (k & 1);
            bool ok = (iy >= 0 && iy < HW && ix >= 0 && ix < HW) && (gp < NPIX);
            pps[tid * 4 + k] = ok ? (iy * HW + ix) : -1;
            float w = ((k >> 1) ? wy1 : wy0) * ((k & 1) ? wx1 : wx0);
            wts[tid * 4 + k] = w;
            if (ok) ws += w;
        }
        wss[tid] = ws;
    }
    __syncthreads();

    const float* hb = g_h1 + (size_t)ib * NPIX * HIDC;
#pragma unroll
    for (int e = 0; e < 16; e++) {
        int idx = tid + e * 256;
        int ch = idx & 63, pix = idx >> 6;
        float a = 0.f;
#pragma unroll
        for (int k = 0; k < 4; k++) {
            int q = pps[pix * 4 + k];
            if (q >= 0) a += wts[pix * 4 + k] * hb[(size_t)q * HIDC + ch];
        }
        Hs[pix * 68 + ch] = a;
    }
    __syncthreads();

    int d = tid & 127;
    float wreg[HIDC];
#pragma unroll
    for (int h = 0; h < HIDC; h++) wreg[h] = w2s[d * 65 + h];
    float bd = b2[d];

#pragma unroll 4
    for (int pass = 0; pass < 32; pass++) {
        int pix = pass * 2 + (tid >> 7);
        int gp = p0 + pix;
        float acc = wss[pix] * bd;
        const float4* hv = (const float4*)&Hs[pix * 68];
#pragma unroll
        for (int h4 = 0; h4 < 16; h4++) {
            float4 hvv = hv[h4];
            acc = fmaf(wreg[h4 * 4 + 0], hvv.x, acc);
            acc = fmaf(wreg[h4 * 4 + 1], hvv.y, acc);
            acc = fmaf(wreg[h4 * 4 + 2], hvv.z, acc);
            acc = fmaf(wreg[h4 * 4 + 3], hvv.w, acc);
        }
        if (gp < NPIX)
            g_Fh[((size_t)ib * NPIX + gp) * FEATC + d] = __float2half_rn(acc);
    }
}

// ---------------- K4: single-term fp16 HMMA GEMM, 128x128, fp16 C (R11 form) ----------------
#define SA_HI 0
#define SBH_OFF 32768
#define GEMM_SMEM 65536
__device__ __forceinline__ uint32_t sw_off(int r, int c16) {
    return (uint32_t)(r * 256 + ((((c16 ^ r) & 7)) | (c16 & 8)) * 16);
}
__device__ __forceinline__ uint32_t smem_u32(const void* p) {
    uint32_t a;
    asm("{ .reg .u64 t; cvta.to.shared.u64 t, %1; cvt.u32.u64 %0, t; }" : "=r"(a) : "l"(p));
    return a;
}
#define LDSM_X4(R0, R1, R2, R3, addr)                                             \
    asm volatile("ldmatrix.sync.aligned.m8n8.x4.shared.b16 {%0,%1,%2,%3}, [%4];"  \
                 : "=r"(R0), "=r"(R1), "=r"(R2), "=r"(R3) : "r"(addr))
#define HMMA16816(D, A0, A1, A2, A3, B0, B1)                                      \
    asm volatile("mma.sync.aligned.m16n8k16.row.col.f32.f16.f16.f32 "             \
                 "{%0,%1,%2,%3}, {%4,%5,%6,%7}, {%8,%9}, {%0,%1,%2,%3};\n"        \
                 : "+f"(D[0]), "+f"(D[1]), "+f"(D[2]), "+f"(D[3])                 \
                 : "r"(A0), "r"(A1), "r"(A2), "r"(A3), "r"(B0), "r"(B1))

__global__ __launch_bounds__(256, 2) void gemm_hmma_kernel() {
    extern __shared__ char smem[];
    uint32_t sb = smem_u32(smem);
    int z = blockIdx.z;
    int mat = z >> 2, b = z & 3;
    size_t baseA = (size_t)((mat * 2)     * 4 + b) * NPIX * FEATC;
    size_t baseB = (size_t)((mat * 2 + 1) * 4 + b) * NPIX * FEATC;
    __half* C = g_M + (size_t)z * MSIZE;
    int n0 = blockIdx.y * 128, m0 = blockIdx.x * 128;
    int tid = threadIdx.x;
    int wid = tid >> 5, lane = tid & 31;
    int wr = wid >> 2, wc = wid & 3;

    // ---- copy A, B (2 x 2048 uint4) ----
    {
        const uint4* srcA = (const uint4*)(g_Fh + baseA);
        const uint4* srcB = (const uint4*)(g_Fh + baseB);
#pragma unroll
        for (int i = 0; i < 8; i++) {
            int slot = tid + i * 256;
            int c16 = slot & 15, row = slot >> 4;
            int gr = n0 + row, gm = m0 + row;
            uint4 va = make_uint4(0, 0, 0, 0), vb = va;
            if (gr < NPIX) va = srcA[gr * 16 + c16];
            if (gm < NPIX) vb = srcB[gm * 16 + c16];
            uint32_t o = sw_off(row, c16);
            *(uint4*)(smem + SA_HI  + o) = va;
            *(uint4*)(smem + SBH_OFF + o) = vb;
        }
    }
    __syncthreads();

    float acc[4][4][4];
#pragma unroll
    for (int u = 0; u < 4; u++)
#pragma unroll
        for (int v = 0; v < 4; v++)
#pragma unroll
            for (int r = 0; r < 4; r++) acc[u][v][r] = 0.f;

    int a_row_l = ((lane >> 3) & 1) * 8 + (lane & 7);
    int a_c16_l = (lane >> 4);
    int b_row_l = ((lane >> 4) * 8) + (lane & 7);
    int b_c16_l = ((lane >> 3) & 1);

#pragma unroll
    for (int kt = 0; kt < 8; kt++) {
        uint32_t ah[4][4], bh[4][2];
#pragma unroll
        for (int mt = 0; mt < 4; mt++) {
            uint32_t off = sw_off(wr * 64 + mt * 16 + a_row_l, 2 * kt + a_c16_l);
            LDSM_X4(ah[mt][0], ah[mt][1], ah[mt][2], ah[mt][3], sb + SA_HI + off);
        }
#pragma unroll
        for (int np = 0; np < 2; np++) {
            uint32_t off = sw_off(wc * 32 + np * 16 + b_row_l, 2 * kt + b_c16_l);
            LDSM_X4(bh[np * 2][0], bh[np * 2][1], bh[np * 2 + 1][0], bh[np * 2 + 1][1], sb + SBH_OFF + off);
        }
#pragma unroll
        for (int mt = 0; mt < 4; mt++)
#pragma unroll
            for (int nt = 0; nt < 4; nt++)
                HMMA16816(acc[mt][nt], ah[mt][0], ah[mt][1], ah[mt][2], ah[mt][3], bh[nt][0], bh[nt][1]);
    }

    // ---- store C (fp16, default policy) ----
    int g = lane >> 2, t4 = lane & 3;
#pragma unroll
    for (int mt = 0; mt < 4; mt++) {
        int r0 = n0 + wr * 64 + mt * 16 + g;
#pragma unroll
        for (int nt = 0; nt < 4; nt++) {
            int col = m0 + wc * 32 + nt * 8 + 2 * t4;
            if (col < NPIX) {
                if (r0 < NPIX)
                    *(__half2*)&C[(size_t)r0 * NPIX + col] = __floats2half2_rn(acc[mt][nt][0], acc[mt][nt][1]);
                if (r0 + 8 < NPIX)
                    *(__half2*)&C[(size_t)(r0 + 8) * NPIX + col] = __floats2half2_rn(acc[mt][nt][2], acc[mt][nt][3]);
            }
        }
    }

    // ---- fused per-tile softmax stats ----
    __syncthreads();
    float* s_a   = (float*)smem;
    float* s_fin = (float*)smem + 512;

    if (mat == 0) {
        float rmx[4][2];
#pragma unroll
        for (int mt = 0; mt < 4; mt++)
#pragma unroll
            for (int h = 0; h < 2; h++) {
                float v = -1e30f;
#pragma unroll
                for (int nt = 0; nt < 4; nt++)
#pragma unroll
                    for (int k = 0; k < 2; k++) {
                        int col = m0 + wc * 32 + nt * 8 + 2 * t4 + k;
                        float x = (col < NPIX) ? acc[mt][nt][h * 2 + k] : -1e30f;
                        v = fmaxf(v, x);
                    }
                rmx[mt][h] = v;
            }
#pragma unroll
        for (int o = 1; o < 4; o <<= 1)
#pragma unroll
            for (int mt = 0; mt < 4; mt++)
#pragma unroll
                for (int h = 0; h < 2; h++)
                    rmx[mt][h] = fmaxf(rmx[mt][h], __shfl_xor_sync(0xffffffffu, rmx[mt][h], o));
        if (t4 == 0)
#pragma unroll
            for (int mt = 0; mt < 4; mt++)
#pragma unroll
                for (int h = 0; h < 2; h++)
                    s_a[wc * 128 + wr * 64 + mt * 16 + h * 8 + g] = rmx[mt][h];
        __syncthreads();
        if (tid < 128)
            s_fin[tid] = fmaxf(fmaxf(s_a[tid], s_a[128 + tid]), fmaxf(s_a[256 + tid], s_a[384 + tid]));
        __syncthreads();
        float rsm[4][2];
#pragma unroll
        for (int mt = 0; mt < 4; mt++)
#pragma unroll
            for (int h = 0; h < 2; h++) {
                float fm = s_fin[wr * 64 + mt * 16 + h * 8 + g];
                float sa = 0.f;
#pragma unroll
                for (int nt = 0; nt < 4; nt++)
#pragma unroll
                    for (int k = 0; k < 2; k++) {
                        int col = m0 + wc * 32 + nt * 8 + 2 * t4 + k;
                        float x = (col < NPIX) ? acc[mt][nt][h * 2 + k] : -1e30f;
                        sa += fexp(x - fm);
                    }
                rsm[mt][h] = sa;
            }
#pragma unroll
        for (int o = 1; o < 4; o <<= 1)
#pragma unroll
            for (int mt = 0; mt < 4; mt++)
#pragma unroll
                for (int h = 0; h < 2; h++)
                    rsm[mt][h] += __shfl_xor_sync(0xffffffffu, rsm[mt][h], o);
        __syncthreads();
        if (t4 == 0)
#pragma unroll
            for (int mt = 0; mt < 4; mt++)
#pragma unroll
                for (int h = 0; h < 2; h++)
                    s_a[wc * 128 + wr * 64 + mt * 16 + h * 8 + g] = rsm[mt][h];
        __syncthreads();
        if (tid < 128) {
            int n = n0 + tid;
            if (n < NPIX) {
                int o = (blockIdx.x * 4 + b) * NPIX + n;
                g_rmax_p[o] = s_fin[tid];
                g_rsum_p[o] = s_a[tid] + s_a[128 + tid] + s_a[256 + tid] + s_a[384 + tid];
            }
        }
    } else {
        float cmx[4][2];
#pragma unroll
        for (int nt = 0; nt < 4; nt++)
#pragma unroll
            for (int k = 0; k < 2; k++) {
                float v = -1e30f;
#pragma unroll
                for (int mt = 0; mt < 4; mt++)
#pragma unroll
                    for (int h = 0; h < 2; h++) {
                        int row = n0 + wr * 64 + mt * 16 + h * 8 + g;
                        float x = (row < NPIX) ? acc[mt][nt][h * 2 + k] : -1e30f;
                        v = fmaxf(v, x);
                    }
                cmx[nt][k] = v;
            }
#pragma unroll
        for (int o = 4; o < 32; o <<= 1)
#pragma unroll
            for (int nt = 0; nt < 4; nt++)
#pragma unroll
                for (int k = 0; k < 2; k++)
                    cmx[nt][k] = fmaxf(cmx[nt][k], __shfl_xor_sync(0xffffffffu, cmx[nt][k], o));
        if (g == 0)
#pragma unroll
            for (int nt = 0; nt < 4; nt++)
#pragma unroll
                for (int k = 0; k < 2; k++)
                    s_a[wr * 128 + wc * 32 + nt * 8 + 2 * t4 + k] = cmx[nt][k];
        __syncthreads();
        if (tid < 128)
            s_fin[tid] = fmaxf(fmaxf(s_a[tid], s_a[128 + tid]), fmaxf(s_a[256 + tid], s_a[384 + tid]));
        __syncthreads();
        float csm[4][2];
#pragma unroll
        for (int nt = 0; nt < 4; nt++)
#pragma unroll
            for (int k = 0; k < 2; k++) {
                float fm = s_fin[wc * 32 + nt * 8 + 2 * t4 + k];
                float sa = 0.f;
#pragma unroll
                for (int mt = 0; mt < 4; mt++)
#pragma unroll
                    for (int h = 0; h < 2; h++) {
                        int row = n0 + wr * 64 + mt * 16 + h * 8 + g;
                        float x = (row < NPIX) ? acc[mt][nt][h * 2 + k] : -1e30f;
                        sa += fexp(x - fm);
                    }
                csm[nt][k] = sa;
            }
#pragma unroll
        for (int o = 4; o < 32; o <<= 1)
#pragma unroll
            for (int nt = 0; nt < 4; nt++)
#pragma unroll
                for (int k = 0; k < 2; k++)
                    csm[nt][k] += __shfl_xor_sync(0xffffffffu, csm[nt][k], o);
        __syncthreads();
        if (g == 0)
#pragma unroll
            for (int nt = 0; nt < 4; nt++)
#pragma unroll
                for (int k = 0; k < 2; k++)
                    s_a[wr * 128 + wc * 32 + nt * 8 + 2 * t4 + k] = csm[nt][k];
        __syncthreads();
        if (tid < 128) {
            int m = m0 + tid;
            if (m < NPIX) {
                int o = (blockIdx.y * 4 + b) * NPIX + m;
                g_cmax_p[o] = s_fin[tid];
                g_csum_p[o] = s_a[tid] + s_a[128 + tid] + s_a[256 + tid] + s_a[384 + tid];
            }
        }
    }
}

// ---------------- K5: merge row+col partials (fused) ----------------
__global__ void merge_kernel() {
    int idx = blockIdx.x * blockDim.x + threadIdx.x;
    int which = idx / (4 * NPIX);
    int sub = idx % (4 * NPIX);
    if (idx >= 8 * NPIX) return;
    if (which == 0) {
        float mx = -1e30f;
#pragma unroll
        for (int t = 0; t < NTIL; t++) mx = fmaxf(mx, g_rmax_p[t * 4 * NPIX + sub]);
        float s = 0.f;
#pragma unroll
        for (int t = 0; t < NTIL; t++)
            s += g_rsum_p[t * 4 * NPIX + sub] * fexp(g_rmax_p[t * 4 * NPIX + sub] - mx);
        g_hmax[sub] = mx;
        g_hs[sub]   = 1.f / (s + 1e-4f);
    } else {
        float mx = -1e30f;
#pragma unroll
        for (int t = 0; t < NTIL; t++) mx = fmaxf(mx, g_cmax_p[t * 4 * NPIX + sub]);
        float s = 0.f;
#pragma unroll
        for (int t = 0; t < NTIL; t++)
            s += g_csum_p[t * 4 * NPIX + sub] * fexp(g_cmax_p[t * 4 * NPIX + sub] - mx);
        g_vmax[sub] = mx;
        g_vs[sub]   = 1.f / (s + 1e-4f);
    }
}

// ---------------- K6: S[b,m] partial sums (R11 scalar __ldcs form) ----------------
__global__ void spart_kernel() {
    int m = blockIdx.x * 256 + threadIdx.x;
    int b = blockIdx.y, seg = blockIdx.z;
    if (m >= NPIX) return;
    const __half* Mh = g_M + (size_t)b * MSIZE;
    const __half* Mv = g_M + (size_t)(4 + b) * MSIZE;
    float vmaxm = g_vmax[b * NPIX + m];
    float s = 0.f;
    int n0 = seg * SEGN;
    for (int nb = 0; nb < SEGN; nb += 6) {
        float e[6];
#pragma unroll
        for (int j = 0; j < 6; j++) {
            int n = n0 + nb + j;
            float a = __half2float(__ldcs(&Mv[(size_t)n * NPIX + m]));
            float c = __half2float(__ldcs(&Mh[(size_t)n * NPIX + m]));
            e[j] = a + c - g_hmax[b * NPIX + n];
        }
#pragma unroll
        for (int j = 0; j < 6; j++)
            s = fmaf(fexp(e[j] - vmaxm), g_hs[b * NPIX + n0 + nb + j], s);
    }
    g_Spart[(seg * 4 + b) * NPIX + m] = s;
}

// ---------------- K7a: parallel log partials ----------------
__global__ void fpart_kernel() {
    __shared__ float red[256];
    int blk = blockIdx.x;
    int t = threadIdx.x;
    int base = blk * (4 * NPIX / FBLK);
    float acc = 0.f;
    if (t < 240) {
        int idx = base + t;
        int b = idx / NPIX, m = idx % NPIX;
        float S = 0.f;
#pragma unroll
        for (int seg = 0; seg < SEG; seg++) S += g_Spart[(seg * 4 + b) * NPIX + m];
        acc = logf(S * g_vs[idx] + 1e-4f);
    }
    red[t] = acc; __syncthreads();
    for (int s = 128; s > 0; s >>= 1) { if (t < s) red[t] += red[t + s]; __syncthreads(); }
    if (t == 0) g_fpart[blk] = red[0];
}

// ---------------- K7b: deterministic final merge ----------------
__global__ void final_kernel(float* __restrict__ out) {
    __shared__ float red[64];
    int t = threadIdx.x;
    float acc = (t < FBLK) ? g_fpart[t] : 0.f;
    red[t] = acc; __syncthreads();
    for (int s = 32; s > 0; s >>= 1) { if (t < s) red[t] += red[t + s]; __syncthreads(); }
    if (t == 0) out[0] = red[0] * (1.f / (4.f * NPIX));
}

// ---------------- launch ----------------
extern "C" void kernel_launch(void* const* d_in, const int* in_sizes, int n_in,
                              void* d_out, int out_size) {
    const float* input_a = (const float*)d_in[0];
    const float* input_b = (const float*)d_in[1];
    const float* w1      = (const float*)d_in[2];
    const float* b1      = (const float*)d_in[3];
    const float* w2      = (const float*)d_in[4];
    const float* b2      = (const float*)d_in[5];
    const float* noise   = (const float*)d_in[6];
    const int*   u_roll  = (const int*)d_in[7];
    const int*   v_roll  = (const int*)d_in[8];
    const int*   swap    = (const int*)d_in[9];
    float* out = (float*)d_out;

    cudaFuncSetAttribute(gemm_hmma_kernel, cudaFuncAttributeMaxDynamicSharedMemorySize, GEMM_SMEM);
    cudaFuncSetAttribute(bwdconv1_kernel, cudaFuncAttributeMaxDynamicSharedMemorySize, BW_SMEM);

    fwd_sample_kernel<<<(16 * 3 * NPIX + 255) / 256, 256>>>(input_a, input_b, noise, swap, u_roll, v_roll);
    conv3_kernel<<<(16 * HIDC * NPIX + 255) / 256, 256>>>(w1, b1);
    bwdconv1_kernel<<<dim3((NPIX + PIXB - 1) / PIXB, 16), 256, BW_SMEM>>>(w2, b2, noise, swap, u_roll, v_roll);
    gemm_hmma_kernel<<<dim3(NTIL, NTIL, 8), 256, GEMM_SMEM>>>();
    merge_kernel<<<(8 * NPIX + 255) / 256, 256>>>();
    spart_kernel<<<dim3(15, 4, SEG), 256>>>();
    fpart_kernel<<<FBLK, 256>>>();
    final_kernel<<<1, 64>>>(out);
}

// round 16
// speedup vs baseline: 1.2105x; 1.0947x over previous
#include <cuda_runtime.h>
#include <cuda_fp16.h>
#include <stdint.h>

#define HW    60
#define NPIX  3600
#define HIDC  64
#define FEATC 128
#define MSIZE (3600LL*3600LL)
#define SEG   16
#define SEGN  225   /* 3600/16 */
#define NTIL  29    /* ceil(3600/128) */
#define PIXB  64    /* pixels per bwdconv1 block */
#define FBLK  60    /* final partial blocks */

// ---------------- static device scratch (no allocations allowed) ----------------
__device__ float g_xw[16*3*NPIX];            // forward-warped inputs
__device__ float g_h1[16L*NPIX*HIDC];        // conv3x3+relu, TRANSPOSED: [ib][pix][ch]
__device__ __half g_Fh[16L*NPIX*FEATC];      // features (fp16)
__device__ __half g_M [8L*3600*3600];        // [mat*4+b][n][m]  fp16 (~207MB)
__device__ float g_rmax_p[NTIL*4*NPIX], g_rsum_p[NTIL*4*NPIX];
__device__ float g_cmax_p[NTIL*4*NPIX], g_csum_p[NTIL*4*NPIX];
__device__ float g_hmax[4*NPIX], g_hs[4*NPIX];
__device__ float g_vmax[4*NPIX], g_vs[4*NPIX];
__device__ float g_Spart[SEG*4*NPIX];
__device__ float g_fpart[FBLK];

// Fast exp on the FMA pipe (no MUFU). rel err ~2e-5.
__device__ __forceinline__ float fexp(float x) {
    float t = x * 1.4426950408889634f;
    t = fmaxf(t, -125.0f);
    float r = floorf(t);
    float f = t - r;
    float p = 1.5403530e-4f;
    p = fmaf(p, f, 1.3333558e-3f);
    p = fmaf(p, f, 9.6181291e-3f);
    p = fmaf(p, f, 5.5504109e-2f);
    p = fmaf(p, f, 2.4022651e-1f);
    p = fmaf(p, f, 6.9314718e-1f);
    p = fmaf(p, f, 1.0f);
    int ei = (int)r;
    return __int_as_float((ei + 127) << 23) * p;
}

__device__ __forceinline__ void compute_theta(const float* __restrict__ noise, int swp, int ib,
                                              float* TA, float* TB) {
    const float* nz = noise + ib * 9;
    float a  = 1.f + 0.05f * nz[0], b = 0.05f * nz[1], c = 0.05f * nz[2];
    float d  = 0.05f * nz[3], e = 1.f + 0.05f * nz[4], f = 0.05f * nz[5];
    float id = 1.f / (a * e - b * d);
    float fwd[6] = {a, b, c, d, e, f};
    float bwd[6] = { e * id, -b * id, (b * f - c * e) * id,
                    -d * id,  a * id, (c * d - a * f) * id};
    bool s = (swp == 1);
#pragma unroll
    for (int k = 0; k < 6; k++) {
        if (TA) TA[k] = s ? bwd[k] : fwd[k];
        if (TB) TB[k] = s ? fwd[k] : bwd[k];
    }
}

// ---------------- K1: forward grid_sample ----------------
__global__ void fwd_sample_kernel(const float* __restrict__ inA, const float* __restrict__ inB,
                                  const float* __restrict__ noise, const int* __restrict__ swap,
                                  const int* __restrict__ u_roll, const int* __restrict__ v_roll) {
    int idx = blockIdx.x * blockDim.x + threadIdx.x;
    if (idx >= 16 * 3 * NPIX) return;
    int p  = idx % NPIX;
    int c  = (idx / NPIX) % 3;
    int ib = idx / (3 * NPIX);
    int i  = ib >> 2, b = ib & 3;
    float T[6];
    compute_theta(noise, swap[i], ib, T, nullptr);
    int r = p / HW, cc = p % HW;
    float xn = (2 * cc + 1) * (1.f / HW) - 1.f;
    float yn = (2 * r  + 1) * (1.f / HW) - 1.f;
    float gx = T[0] * xn + T[1] * yn + T[2];
    float gy = T[3] * xn + T[4] * yn + T[5];
    float x = (gx + 1.f) * (HW * 0.5f) - 0.5f;
    float y = (gy + 1.f) * (HW * 0.5f) - 0.5f;
    float x0f = floorf(x), y0f = floorf(y);
    int x0 = (int)x0f, y0 = (int)y0f;
    float wx1 = x - x0f, wx0 = 1.f - wx1;
    float wy1 = y - y0f, wy0 = 1.f - wy1;
    const float* src = ((i & 1) == 0) ? inA : inB;
    src += (b * 3 + c) * NPIX;
    int u = u_roll[ib], v = v_roll[ib];
    float acc = 0.f;
#pragma unroll
    for (int ky = 0; ky < 2; ky++) {
        int iy = y0 + ky;
        if (iy < 0 || iy >= HW) continue;
        int ry = iy + u; if (ry >= HW) ry -= HW;
        float wy = ky ? wy1 : wy0;
#pragma unroll
        for (int kx = 0; kx < 2; kx++) {
            int ix = x0 + kx;
            if (ix < 0 || ix >= HW) continue;
            int rx = ix + v; if (rx >= HW) rx -= HW;
            acc += wy * (kx ? wx1 : wx0) * src[ry * HW + rx];
        }
    }
    g_xw[ib * 3 * NPIX + c * NPIX + p] = acc;
}

// ---------------- K2: conv3x3 (3->64) + relu, transposed out (R11 form) ----------------
__global__ void conv3_kernel(const float* __restrict__ w1, const float* __restrict__ b1) {
    int idx = blockIdx.x * blockDim.x + threadIdx.x;
    if (idx >= 16 * HIDC * NPIX) return;
    int p  = idx % NPIX;
    int oc = (idx / NPIX) % HIDC;
    int ib = idx / (NPIX * HIDC);
    int r = p / HW, c = p % HW;
    const float* xin = g_xw + ib * 3 * NPIX;
    const float* wk  = w1 + oc * 27;
    float acc = b1[oc];
#pragma unroll
    for (int ci = 0; ci < 3; ci++)
#pragma unroll
        for (int dy = -1; dy <= 1; dy++) {
            int rr = r + dy;
            if (rr < 0 || rr >= HW) continue;
#pragma unroll
            for (int dx = -1; dx <= 1; dx++) {
                int c2 = c + dx;
                if (c2 < 0 || c2 >= HW) continue;
                acc += wk[ci * 9 + (dy + 1) * 3 + (dx + 1)] * xin[ci * NPIX + rr * HW + c2];
            }
        }
    g_h1[((size_t)ib * NPIX + p) * HIDC + oc] = fmaxf(acc, 0.f);
}

// ---------------- K3: fused backward grid_sample + conv1x1 (dynamic smem) ----------------
#define BW_W2S   0
#define BW_HS    (FEATC * 65)
#define BW_WTS   (BW_HS + PIXB * 68)
#define BW_WSS   (BW_WTS + PIXB * 4)
#define BW_PPS   (BW_WSS + PIXB)
#define BW_SMEM  ((BW_PPS + PIXB * 4) * 4)
__global__ __launch_bounds__(256) void bwdconv1_kernel(
        const float* __restrict__ w2, const float* __restrict__ b2,
        const float* __restrict__ noise, const int* __restrict__ swap,
        const int* __restrict__ u_roll, const int* __restrict__ v_roll) {
    extern __shared__ float smf[];
    float* w2s = smf + BW_W2S;
    float* Hs  = smf + BW_HS;
    float* wts = smf + BW_WTS;
    float* wss = smf + BW_WSS;
    int*   pps = (int*)(smf + BW_PPS);

    int ib = blockIdx.y;
    int p0 = blockIdx.x * PIXB;
    int tid = threadIdx.x;

    for (int i = tid; i < FEATC * HIDC; i += 256)
        w2s[(i >> 6) * 65 + (i & 63)] = w2[i];

    if (tid < PIXB) {
        int gp = p0 + tid;
        float T[6];
        compute_theta(noise, swap[ib >> 2], ib, nullptr, T);
        int u = u_roll[ib], v = v_roll[ib];
        int n = (gp < NPIX) ? gp : NPIX - 1;
        int r = n / HW, c = n % HW;
        int rr = r - u; if (rr < 0) rr += HW;
        int cc = c - v; if (cc < 0) cc += HW;
        float xn = (2 * cc + 1) * (1.f / HW) - 1.f;
        float yn = (2 * rr + 1) * (1.f / HW) - 1.f;
        float gx = T[0] * xn + T[1] * yn + T[2];
        float gy = T[3] * xn + T[4] * yn + T[5];
        float x = (gx + 1.f) * (HW * 0.5f) - 0.5f;
        float y = (gy + 1.f) * (HW * 0.5f) - 0.5f;
        float x0f = floorf(x), y0f = floorf(y);
        int x0 = (int)x0f, y0 = (int)y0f;
        float wx1 = x - x0f, wx0 = 1.f - wx1;
        float wy1 = y - y0f, wy0 = 1.f - wy1;
        float ws = 0.f;
#pragma unroll
        for (int k = 0; k < 4; k++) {
            int iy = y0 + (k >> 1), ix = x0 + (k & 1);
            bool ok = (iy >= 0 && iy < HW && ix >= 0 && ix < HW) && (gp < NPIX);
            pps[tid * 4 + k] = ok ? (iy * HW + ix) : -1;
            float w = ((k >> 1) ? wy1 : wy0) * ((k & 1) ? wx1 : wx0);
            wts[tid * 4 + k] = w;
            if (ok) ws += w;
        }
        wss[tid] = ws;
    }
    __syncthreads();

    const float* hb = g_h1 + (size_t)ib * NPIX * HIDC;
#pragma unroll
    for (int e = 0; e < 16; e++) {
        int idx = tid + e * 256;
        int ch = idx & 63, pix = idx >> 6;
        float a = 0.f;
#pragma unroll
        for (int k = 0; k < 4; k++) {
            int q = pps[pix * 4 + k];
            if (q >= 0) a += wts[pix * 4 + k] * hb[(size_t)q * HIDC + ch];
        }
        Hs[pix * 68 + ch] = a;
    }
    __syncthreads();

    int d = tid & 127;
    float wreg[HIDC];
#pragma unroll
    for (int h = 0; h < HIDC; h++) wreg[h] = w2s[d * 65 + h];
    float bd = b2[d];

#pragma unroll 4
    for (int pass = 0; pass < 32; pass++) {
        int pix = pass * 2 + (tid >> 7);
        int gp = p0 + pix;
        float acc = wss[pix] * bd;
        const float4* hv = (const float4*)&Hs[pix * 68];
#pragma unroll
        for (int h4 = 0; h4 < 16; h4++) {
            float4 hvv = hv[h4];
            acc = fmaf(wreg[h4 * 4 + 0], hvv.x, acc);
            acc = fmaf(wreg[h4 * 4 + 1], hvv.y, acc);
            acc = fmaf(wreg[h4 * 4 + 2], hvv.z, acc);
            acc = fmaf(wreg[h4 * 4 + 3], hvv.w, acc);
        }
        if (gp < NPIX)
            g_Fh[((size_t)ib * NPIX + gp) * FEATC + d] = __float2half_rn(acc);
    }
}

// ---------------- K4: single-term fp16 HMMA GEMM, 128x128, fp16 C (R11 form) ----------------
#define SA_HI 0
#define SBH_OFF 32768
#define GEMM_SMEM 65536
__device__ __forceinline__ uint32_t sw_off(int r, int c16) {
    return (uint32_t)(r * 256 + ((((c16 ^ r) & 7)) | (c16 & 8)) * 16);
}
__device__ __forceinline__ uint32_t smem_u32(const void* p) {
    uint32_t a;
    asm("{ .reg .u64 t; cvta.to.shared.u64 t, %1; cvt.u32.u64 %0, t; }" : "=r"(a) : "l"(p));
    return a;
}
#define LDSM_X4(R0, R1, R2, R3, addr)                                             \
    asm volatile("ldmatrix.sync.aligned.m8n8.x4.shared.b16 {%0,%1,%2,%3}, [%4];"  \
                 : "=r"(R0), "=r"(R1), "=r"(R2), "=r"(R3) : "r"(addr))
#define HMMA16816(D, A0, A1, A2, A3, B0, B1)                                      \
    asm volatile("mma.sync.aligned.m16n8k16.row.col.f32.f16.f16.f32 "             \
                 "{%0,%1,%2,%3}, {%4,%5,%6,%7}, {%8,%9}, {%0,%1,%2,%3};\n"        \
                 : "+f"(D[0]), "+f"(D[1]), "+f"(D[2]), "+f"(D[3])                 \
                 : "r"(A0), "r"(A1), "r"(A2), "r"(A3), "r"(B0), "r"(B1))

__global__ __launch_bounds__(256, 2) void gemm_hmma_kernel() {
    extern __shared__ char smem[];
    uint32_t sb = smem_u32(smem);
    int z = blockIdx.z;
    int mat = z >> 2, b = z & 3;
    size_t baseA = (size_t)((mat * 2)     * 4 + b) * NPIX * FEATC;
    size_t baseB = (size_t)((mat * 2 + 1) * 4 + b) * NPIX * FEATC;
    __half* C = g_M + (size_t)z * MSIZE;
    int n0 = blockIdx.y * 128, m0 = blockIdx.x * 128;
    int tid = threadIdx.x;
    int wid = tid >> 5, lane = tid & 31;
    int wr = wid >> 2, wc = wid & 3;

    // ---- copy A, B (2 x 2048 uint4) ----
    {
        const uint4* srcA = (const uint4*)(g_Fh + baseA);
        const uint4* srcB = (const uint4*)(g_Fh + baseB);
#pragma unroll
        for (int i = 0; i < 8; i++) {
            int slot = tid + i * 256;
            int c16 = slot & 15, row = slot >> 4;
            int gr = n0 + row, gm = m0 + row;
            uint4 va = make_uint4(0, 0, 0, 0), vb = va;
            if (gr < NPIX) va = srcA[gr * 16 + c16];
            if (gm < NPIX) vb = srcB[gm * 16 + c16];
            uint32_t o = sw_off(row, c16);
            *(uint4*)(smem + SA_HI  + o) = va;
            *(uint4*)(smem + SBH_OFF + o) = vb;
        }
    }
    __syncthreads();

    float acc[4][4][4];
#pragma unroll
    for (int u = 0; u < 4; u++)
#pragma unroll
        for (int v = 0; v < 4; v++)
#pragma unroll
            for (int r = 0; r < 4; r++) acc[u][v][r] = 0.f;

    int a_row_l = ((lane >> 3) & 1) * 8 + (lane & 7);
    int a_c16_l = (lane >> 4);
    int b_row_l = ((lane >> 4) * 8) + (lane & 7);
    int b_c16_l = ((lane >> 3) & 1);

#pragma unroll
    for (int kt = 0; kt < 8; kt++) {
        uint32_t ah[4][4], bh[4][2];
#pragma unroll
        for (int mt = 0; mt < 4; mt++) {
            uint32_t off = sw_off(wr * 64 + mt * 16 + a_row_l, 2 * kt + a_c16_l);
            LDSM_X4(ah[mt][0], ah[mt][1], ah[mt][2], ah[mt][3], sb + SA_HI + off);
        }
#pragma unroll
        for (int np = 0; np < 2; np++) {
            uint32_t off = sw_off(wc * 32 + np * 16 + b_row_l, 2 * kt + b_c16_l);
            LDSM_X4(bh[np * 2][0], bh[np * 2][1], bh[np * 2 + 1][0], bh[np * 2 + 1][1], sb + SBH_OFF + off);
        }
#pragma unroll
        for (int mt = 0; mt < 4; mt++)
#pragma unroll
            for (int nt = 0; nt < 4; nt++)
                HMMA16816(acc[mt][nt], ah[mt][0], ah[mt][1], ah[mt][2], ah[mt][3], bh[nt][0], bh[nt][1]);
    }

    // ---- store C (fp16, default policy) ----
    int g = lane >> 2, t4 = lane & 3;
#pragma unroll
    for (int mt = 0; mt < 4; mt++) {
        int r0 = n0 + wr * 64 + mt * 16 + g;
#pragma unroll
        for (int nt = 0; nt < 4; nt++) {
            int col = m0 + wc * 32 + nt * 8 + 2 * t4;
            if (col < NPIX) {
                if (r0 < NPIX)
                    *(__half2*)&C[(size_t)r0 * NPIX + col] = __floats2half2_rn(acc[mt][nt][0], acc[mt][nt][1]);
                if (r0 + 8 < NPIX)
                    *(__half2*)&C[(size_t)(r0 + 8) * NPIX + col] = __floats2half2_rn(acc[mt][nt][2], acc[mt][nt][3]);
            }
        }
    }

    // ---- fused per-tile softmax stats ----
    __syncthreads();
    float* s_a   = (float*)smem;
    float* s_fin = (float*)smem + 512;

    if (mat == 0) {
        float rmx[4][2];
#pragma unroll
        for (int mt = 0; mt < 4; mt++)
#pragma unroll
            for (int h = 0; h < 2; h++) {
                float v = -1e30f;
#pragma unroll
                for (int nt = 0; nt < 4; nt++)
#pragma unroll
                    for (int k = 0; k < 2; k++) {
                        int col = m0 + wc * 32 + nt * 8 + 2 * t4 + k;
                        float x = (col < NPIX) ? acc[mt][nt][h * 2 + k] : -1e30f;
                        v = fmaxf(v, x);
                    }
                rmx[mt][h] = v;
            }
#pragma unroll
        for (int o = 1; o < 4; o <<= 1)
#pragma unroll
            for (int mt = 0; mt < 4; mt++)
#pragma unroll
                for (int h = 0; h < 2; h++)
                    rmx[mt][h] = fmaxf(rmx[mt][h], __shfl_xor_sync(0xffffffffu, rmx[mt][h], o));
        if (t4 == 0)
#pragma unroll
            for (int mt = 0; mt < 4; mt++)
#pragma unroll
                for (int h = 0; h < 2; h++)
                    s_a[wc * 128 + wr * 64 + mt * 16 + h * 8 + g] = rmx[mt][h];
        __syncthreads();
        if (tid < 128)
            s_fin[tid] = fmaxf(fmaxf(s_a[tid], s_a[128 + tid]), fmaxf(s_a[256 + tid], s_a[384 + tid]));
        __syncthreads();
        float rsm[4][2];
#pragma unroll
        for (int mt = 0; mt < 4; mt++)
#pragma unroll
            for (int h = 0; h < 2; h++) {
                float fm = s_fin[wr * 64 + mt * 16 + h * 8 + g];
                float sa = 0.f;
#pragma unroll
                for (int nt = 0; nt < 4; nt++)
#pragma unroll
                    for (int k = 0; k < 2; k++) {
                        int col = m0 + wc * 32 + nt * 8 + 2 * t4 + k;
                        float x = (col < NPIX) ? acc[mt][nt][h * 2 + k] : -1e30f;
                        sa += fexp(x - fm);
                    }
                rsm[mt][h] = sa;
            }
#pragma unroll
        for (int o = 1; o < 4; o <<= 1)
#pragma unroll
            for (int mt = 0; mt < 4; mt++)
#pragma unroll
                for (int h = 0; h < 2; h++)
                    rsm[mt][h] += __shfl_xor_sync(0xffffffffu, rsm[mt][h], o);
        __syncthreads();
        if (t4 == 0)
#pragma unroll
            for (int mt = 0; mt < 4; mt++)
#pragma unroll
                for (int h = 0; h < 2; h++)
                    s_a[wc * 128 + wr * 64 + mt * 16 + h * 8 + g] = rsm[mt][h];
        __syncthreads();
        if (tid < 128) {
            int n = n0 + tid;
            if (n < NPIX) {
                int o = (blockIdx.x * 4 + b) * NPIX + n;
                g_rmax_p[o] = s_fin[tid];
                g_rsum_p[o] = s_a[tid] + s_a[128 + tid] + s_a[256 + tid] + s_a[384 + tid];
            }
        }
    } else {
        float cmx[4][2];
#pragma unroll
        for (int nt = 0; nt < 4; nt++)
#pragma unroll
            for (int k = 0; k < 2; k++) {
                float v = -1e30f;
#pragma unroll
                for (int mt = 0; mt < 4; mt++)
#pragma unroll
                    for (int h = 0; h < 2; h++) {
                        int row = n0 + wr * 64 + mt * 16 + h * 8 + g;
                        float x = (row < NPIX) ? acc[mt][nt][h * 2 + k] : -1e30f;
                        v = fmaxf(v, x);
                    }
                cmx[nt][k] = v;
            }
#pragma unroll
        for (int o = 4; o < 32; o <<= 1)
#pragma unroll
            for (int nt = 0; nt < 4; nt++)
#pragma unroll
                for (int k = 0; k < 2; k++)
                    cmx[nt][k] = fmaxf(cmx[nt][k], __shfl_xor_sync(0xffffffffu, cmx[nt][k], o));
        if (g == 0)
#pragma unroll
            for (int nt = 0; nt < 4; nt++)
#pragma unroll
                for (int k = 0; k < 2; k++)
                    s_a[wr * 128 + wc * 32 + nt * 8 + 2 * t4 + k] = cmx[nt][k];
        __syncthreads();
        if (tid < 128)
            s_fin[tid] = fmaxf(fmaxf(s_a[tid], s_a[128 + tid]), fmaxf(s_a[256 + tid], s_a[384 + tid]));
        __syncthreads();
        float csm[4][2];
#pragma unroll
        for (int nt = 0; nt < 4; nt++)
#pragma unroll
            for (int k = 0; k < 2; k++) {
                float fm = s_fin[wc * 32 + nt * 8 + 2 * t4 + k];
                float sa = 0.f;
#pragma unroll
                for (int mt = 0; mt < 4; mt++)
#pragma unroll
                    for (int h = 0; h < 2; h++) {
                        int row = n0 + wr * 64 + mt * 16 + h * 8 + g;
                        float x = (row < NPIX) ? acc[mt][nt][h * 2 + k] : -1e30f;
                        sa += fexp(x - fm);
                    }
                csm[nt][k] = sa;
            }
#pragma unroll
        for (int o = 4; o < 32; o <<= 1)
#pragma unroll
            for (int nt = 0; nt < 4; nt++)
#pragma unroll
                for (int k = 0; k < 2; k++)
                    csm[nt][k] += __shfl_xor_sync(0xffffffffu, csm[nt][k], o);
        __syncthreads();
        if (g == 0)
#pragma unroll
            for (int nt = 0; nt < 4; nt++)
#pragma unroll
                for (int k = 0; k < 2; k++)
                    s_a[wr * 128 + wc * 32 + nt * 8 + 2 * t4 + k] = csm[nt][k];
        __syncthreads();
        if (tid < 128) {
            int m = m0 + tid;
            if (m < NPIX) {
                int o = (blockIdx.y * 4 + b) * NPIX + m;
                g_cmax_p[o] = s_fin[tid];
                g_csum_p[o] = s_a[tid] + s_a[128 + tid] + s_a[256 + tid] + s_a[384 + tid];
            }
        }
    }
}

// ---------------- K5: merge row+col partials (fused) ----------------
__global__ void merge_kernel() {
    int idx = blockIdx.x * blockDim.x + threadIdx.x;
    int which = idx / (4 * NPIX);
    int sub = idx % (4 * NPIX);
    if (idx >= 8 * NPIX) return;
    if (which == 0) {
        float mx = -1e30f;
#pragma unroll
        for (int t = 0; t < NTIL; t++) mx = fmaxf(mx, g_rmax_p[t * 4 * NPIX + sub]);
        float s = 0.f;
#pragma unroll
        for (int t = 0; t < NTIL; t++)
            s += g_rsum_p[t * 4 * NPIX + sub] * fexp(g_rmax_p[t * 4 * NPIX + sub] - mx);
        g_hmax[sub] = mx;
        g_hs[sub]   = 1.f / (s + 1e-4f);
    } else {
        float mx = -1e30f;
#pragma unroll
        for (int t = 0; t < NTIL; t++) mx = fmaxf(mx, g_cmax_p[t * 4 * NPIX + sub]);
        float s = 0.f;
#pragma unroll
        for (int t = 0; t < NTIL; t++)
            s += g_csum_p[t * 4 * NPIX + sub] * fexp(g_cmax_p[t * 4 * NPIX + sub] - mx);
        g_vmax[sub] = mx;
        g_vs[sub]   = 1.f / (s + 1e-4f);
    }
}

// ---------------- K6: S[b,m] partials, half2 loads + 16 n-segments ----------------
__global__ void spart_kernel() {
    int m2 = blockIdx.x * 256 + threadIdx.x;   // half2 index (2 m's per thread)
    int b = blockIdx.y, seg = blockIdx.z;
    if (m2 >= NPIX / 2) return;
    const __half2* Mh = (const __half2*)(g_M + (size_t)b * MSIZE);
    const __half2* Mv = (const __half2*)(g_M + (size_t)(4 + b) * MSIZE);
    int m = 2 * m2;
    float vm0 = g_vmax[b * NPIX + m], vm1 = g_vmax[b * NPIX + m + 1];
    float s0 = 0.f, s1 = 0.f;
    int n0 = seg * SEGN;
    const int RW = NPIX / 2;                   // half2 row stride
    for (int nb = 0; nb < SEGN; nb += 5) {     // 225 = 45 x 5
        float2 av[5], cv[5];
        float hm[5], hw[5];
#pragma unroll
        for (int j = 0; j < 5; j++) {
            int n = n0 + nb + j;
            av[j] = __half22float2(__ldcs(&Mv[(size_t)n * RW + m2]));
            cv[j] = __half22float2(__ldcs(&Mh[(size_t)n * RW + m2]));
            hm[j] = g_hmax[b * NPIX + n];
            hw[j] = g_hs[b * NPIX + n];
        }
#pragma unroll
        for (int j = 0; j < 5; j++) {
            float base0 = av[j].x + cv[j].x - hm[j];
            float base1 = av[j].y + cv[j].y - hm[j];
            s0 = fmaf(fexp(base0 - vm0), hw[j], s0);
            s1 = fmaf(fexp(base1 - vm1), hw[j], s1);
        }
    }
    *(float2*)&g_Spart[(seg * 4 + b) * NPIX + m] = make_float2(s0, s1);
}

// ---------------- K7a: parallel log partials ----------------
__global__ void fpart_kernel() {
    __shared__ float red[256];
    int blk = blockIdx.x;
    int t = threadIdx.x;
    int base = blk * (4 * NPIX / FBLK);
    float acc = 0.f;
    if (t < 240) {
        int idx = base + t;
        int b = idx / NPIX, m = idx % NPIX;
        float S = 0.f;
#pragma unroll
        for (int seg = 0; seg < SEG; seg++) S += g_Spart[(seg * 4 + b) * NPIX + m];
        acc = logf(S * g_vs[idx] + 1e-4f);
    }
    red[t] = acc; __syncthreads();
    for (int s = 128; s > 0; s >>= 1) { if (t < s) red[t] += red[t + s]; __syncthreads(); }
    if (t == 0) g_fpart[blk] = red[0];
}

// ---------------- K7b: deterministic final merge ----------------
__global__ void final_kernel(float* __restrict__ out) {
    __shared__ float red[64];
    int t = threadIdx.x;
    float acc = (t < FBLK) ? g_fpart[t] : 0.f;
    red[t] = acc; __syncthreads();
    for (int s = 32; s > 0; s >>= 1) { if (t < s) red[t] += red[t + s]; __syncthreads(); }
    if (t == 0) out[0] = red[0] * (1.f / (4.f * NPIX));
}

// ---------------- launch ----------------
extern "C" void kernel_launch(void* const* d_in, const int* in_sizes, int n_in,
                              void* d_out, int out_size) {
    const float* input_a = (const float*)d_in[0];
    const float* input_b = (const float*)d_in[1];
    const float* w1      = (const float*)d_in[2];
    const float* b1      = (const float*)d_in[3];
    const float* w2      = (const float*)d_in[4];
    const float* b2      = (const float*)d_in[5];
    const float* noise   = (const float*)d_in[6];
    const int*   u_roll  = (const int*)d_in[7];
    const int*   v_roll  = (const int*)d_in[8];
    const int*   swap    = (const int*)d_in[9];
    float* out = (float*)d_out;

    cudaFuncSetAttribute(gemm_hmma_kernel, cudaFuncAttributeMaxDynamicSharedMemorySize, GEMM_SMEM);
    cudaFuncSetAttribute(bwdconv1_kernel, cudaFuncAttributeMaxDynamicSharedMemorySize, BW_SMEM);

    fwd_sample_kernel<<<(16 * 3 * NPIX + 255) / 256, 256>>>(input_a, input_b, noise, swap, u_roll, v_roll);
    conv3_kernel<<<(16 * HIDC * NPIX + 255) / 256, 256>>>(w1, b1);
    bwdconv1_kernel<<<dim3((NPIX + PIXB - 1) / PIXB, 16), 256, BW_SMEM>>>(w2, b2, noise, swap, u_roll, v_roll);
    gemm_hmma_kernel<<<dim3(NTIL, NTIL, 8), 256, GEMM_SMEM>>>();
    merge_kernel<<<(8 * NPIX + 255) / 256, 256>>>();
    spart_kernel<<<dim3((NPIX / 2 + 255) / 256, 4, SEG), 256>>>();
    fpart_kernel<<<FBLK, 256>>>();
    final_kernel<<<1, 64>>>(out);
}

// round 17
// speedup vs baseline: 1.2378x; 1.0225x over previous
#include <cuda_runtime.h>
#include <cuda_fp16.h>
#include <stdint.h>

#define HW    60
#define NPIX  3600
#define HIDC  64
#define FEATC 128
#define MSIZE (3600LL*3600LL)
#define SEG   16
#define SEGN  225   /* 3600/16 */
#define NTIL  29    /* ceil(3600/128) */
#define PIXB  64    /* pixels per bwdconv1 block */
#define FBLK  60    /* final partial blocks */

// ---------------- static device scratch (no allocations allowed) ----------------
__device__ float g_xw[16*3*NPIX];            // forward-warped inputs
__device__ float g_h1[16L*NPIX*HIDC];        // conv3x3+relu, TRANSPOSED: [ib][pix][ch]
__device__ __half g_Fh[16L*NPIX*FEATC];      // features (fp16)
__device__ __half g_M [8L*3600*3600];        // [mat*4+b][n][m]  fp16 (~207MB)
__device__ float g_rmax_p[NTIL*4*NPIX], g_rsum_p[NTIL*4*NPIX];
__device__ float g_cmax_p[NTIL*4*NPIX], g_csum_p[NTIL*4*NPIX];
__device__ float g_hmax[4*NPIX], g_hs[4*NPIX];
__device__ float g_vmax[4*NPIX], g_vs[4*NPIX];
__device__ float g_Spart[SEG*4*NPIX];
__device__ float g_fpart[FBLK];

// Fast exp on the FMA pipe (no MUFU). rel err ~2e-5.
__device__ __forceinline__ float fexp(float x) {
    float t = x * 1.4426950408889634f;
    t = fmaxf(t, -125.0f);
    float r = floorf(t);
    float f = t - r;
    float p = 1.5403530e-4f;
    p = fmaf(p, f, 1.3333558e-3f);
    p = fmaf(p, f, 9.6181291e-3f);
    p = fmaf(p, f, 5.5504109e-2f);
    p = fmaf(p, f, 2.4022651e-1f);
    p = fmaf(p, f, 6.9314718e-1f);
    p = fmaf(p, f, 1.0f);
    int ei = (int)r;
    return __int_as_float((ei + 127) << 23) * p;
}

__device__ __forceinline__ void compute_theta(const float* __restrict__ noise, int swp, int ib,
                                              float* TA, float* TB) {
    const float* nz = noise + ib * 9;
    float a  = 1.f + 0.05f * nz[0], b = 0.05f * nz[1], c = 0.05f * nz[2];
    float d  = 0.05f * nz[3], e = 1.f + 0.05f * nz[4], f = 0.05f * nz[5];
    float id = 1.f / (a * e - b * d);
    float fwd[6] = {a, b, c, d, e, f};
    float bwd[6] = { e * id, -b * id, (b * f - c * e) * id,
                    -d * id,  a * id, (c * d - a * f) * id};
    bool s = (swp == 1);
#pragma unroll
    for (int k = 0; k < 6; k++) {
        if (TA) TA[k] = s ? bwd[k] : fwd[k];
        if (TB) TB[k] = s ? fwd[k] : bwd[k];
    }
}

// ---------------- K1: forward grid_sample ----------------
__global__ void fwd_sample_kernel(const float* __restrict__ inA, const float* __restrict__ inB,
                                  const float* __restrict__ noise, const int* __restrict__ swap,
                                  const int* __restrict__ u_roll, const int* __restrict__ v_roll) {
    int idx = blockIdx.x * blockDim.x + threadIdx.x;
    if (idx >= 16 * 3 * NPIX) return;
    int p  = idx % NPIX;
    int c  = (idx / NPIX) % 3;
    int ib = idx / (3 * NPIX);
    int i  = ib >> 2, b = ib & 3;
    float T[6];
    compute_theta(noise, swap[i], ib, T, nullptr);
    int r = p / HW, cc = p % HW;
    float xn = (2 * cc + 1) * (1.f / HW) - 1.f;
    float yn = (2 * r  + 1) * (1.f / HW) - 1.f;
    float gx = T[0] * xn + T[1] * yn + T[2];
    float gy = T[3] * xn + T[4] * yn + T[5];
    float x = (gx + 1.f) * (HW * 0.5f) - 0.5f;
    float y = (gy + 1.f) * (HW * 0.5f) - 0.5f;
    float x0f = floorf(x), y0f = floorf(y);
    int x0 = (int)x0f, y0 = (int)y0f;
    float wx1 = x - x0f, wx0 = 1.f - wx1;
    float wy1 = y - y0f, wy0 = 1.f - wy1;
    const float* src = ((i & 1) == 0) ? inA : inB;
    src += (b * 3 + c) * NPIX;
    int u = u_roll[ib], v = v_roll[ib];
    float acc = 0.f;
#pragma unroll
    for (int ky = 0; ky < 2; ky++) {
        int iy = y0 + ky;
        if (iy < 0 || iy >= HW) continue;
        int ry = iy + u; if (ry >= HW) ry -= HW;
        float wy = ky ? wy1 : wy0;
#pragma unroll
        for (int kx = 0; kx < 2; kx++) {
            int ix = x0 + kx;
            if (ix < 0 || ix >= HW) continue;
            int rx = ix + v; if (rx >= HW) rx -= HW;
            acc += wy * (kx ? wx1 : wx0) * src[ry * HW + rx];
        }
    }
    g_xw[ib * 3 * NPIX + c * NPIX + p] = acc;
}

// ---------------- K2: conv3x3 (3->64) + relu, oc-fast + smem w1 ----------------
// block: 4 pixels x 64 oc; grid: (NPIX/4, 16)
__global__ __launch_bounds__(256) void conv3_kernel(const float* __restrict__ w1, const float* __restrict__ b1) {
    __shared__ float w1s[HIDC * 27];
    __shared__ float b1s[HIDC];
    int tid = threadIdx.x;
    int ib = blockIdx.y;
    int p0 = blockIdx.x * 4;

    for (int i = tid; i < HIDC * 27; i += 256) w1s[i] = w1[i];
    if (tid < HIDC) b1s[tid] = b1[tid];
    __syncthreads();

    int oc  = tid & 63;
    int pix = tid >> 6;
    int p = p0 + pix;
    int r = p / HW, c = p % HW;
    const float* xin = g_xw + ib * 3 * NPIX;    // warp-uniform reads (broadcast)
    const float* wk  = w1s + oc * 27;           // conflict-free LDS (27 coprime 32)
    float acc = b1s[oc];
#pragma unroll
    for (int ci = 0; ci < 3; ci++)
#pragma unroll
        for (int dy = -1; dy <= 1; dy++) {
            int rr = r + dy;
            if (rr < 0 || rr >= HW) continue;
#pragma unroll
            for (int dx = -1; dx <= 1; dx++) {
                int c2 = c + dx;
                if (c2 < 0 || c2 >= HW) continue;
                acc += wk[ci * 9 + (dy + 1) * 3 + (dx + 1)] * xin[ci * NPIX + rr * HW + c2];
            }
        }
    g_h1[((size_t)ib * NPIX + p) * HIDC + oc] = fmaxf(acc, 0.f);   // coalesced
}

// ---------------- K3: fused backward grid_sample + conv1x1 (dynamic smem) ----------------
#define BW_W2S   0
#define BW_HS    (FEATC * 65)
#define BW_WTS   (BW_HS + PIXB * 68)
#define BW_WSS   (BW_WTS + PIXB * 4)
#define BW_PPS   (BW_WSS + PIXB)
#define BW_SMEM  ((BW_PPS + PIXB * 4) * 4)
__global__ __launch_bounds__(256) void bwdconv1_kernel(
        const float* __restrict__ w2, const float* __restrict__ b2,
        const float* __restrict__ noise, const int* __restrict__ swap,
        const int* __restrict__ u_roll, const int* __restrict__ v_roll) {
    extern __shared__ float smf[];
    float* w2s = smf + BW_W2S;
    float* Hs  = smf + BW_HS;
    float* wts = smf + BW_WTS;
    float* wss = smf + BW_WSS;
    int*   pps = (int*)(smf + BW_PPS);

    int ib = blockIdx.y;
    int p0 = blockIdx.x * PIXB;
    int tid = threadIdx.x;

    for (int i = tid; i < FEATC * HIDC; i += 256)
        w2s[(i >> 6) * 65 + (i & 63)] = w2[i];

    if (tid < PIXB) {
        int gp = p0 + tid;
        float T[6];
        compute_theta(noise, swap[ib >> 2], ib, nullptr, T);
        int u = u_roll[ib], v = v_roll[ib];
        int n = (gp < NPIX) ? gp : NPIX - 1;
        int r = n / HW, c = n % HW;
        int rr = r - u; if (rr < 0) rr += HW;
        int cc = c - v; if (cc < 0) cc += HW;
        float xn = (2 * cc + 1) * (1.f / HW) - 1.f;
        float yn = (2 * rr + 1) * (1.f / HW) - 1.f;
        float gx = T[0] * xn + T[1] * yn + T[2];
        float gy = T[3] * xn + T[4] * yn + T[5];
        float x = (gx + 1.f) * (HW * 0.5f) - 0.5f;
        float y = (gy + 1.f) * (HW * 0.5f) - 0.5f;
        float x0f = floorf(x), y0f = floorf(y);
        int x0 = (int)x0f, y0 = (int)y0f;
        float wx1 = x - x0f, wx0 = 1.f - wx1;
        float wy1 = y - y0f, wy0 = 1.f - wy1;
        float ws = 0.f;
#pragma unroll
        for (int k = 0; k < 4; k++) {
            int iy = y0 + (k >> 1), ix = x0 + (k & 1);
            bool ok = (iy >= 0 && iy < HW && ix >= 0 && ix < HW) && (gp < NPIX);
            pps[tid * 4 + k] = ok ? (iy * HW + ix) : -1;
            float w = ((k >> 1) ? wy1 : wy0) * ((k & 1) ? wx1 : wx0);
            wts[tid * 4 + k] = w;
            if (ok) ws += w;
        }
        wss[tid] = ws;
    }
    __syncthreads();

    const float* hb = g_h1 + (size_t)ib * NPIX * HIDC;
#pragma unroll
    for (int e = 0; e < 16; e++) {
        int idx = tid + e * 256;
        int ch = idx & 63, pix = idx >> 6;
        float a = 0.f;
#pragma unroll
        for (int k = 0; k < 4; k++) {
            int q = pps[pix * 4 + k];
            if (q >= 0) a += wts[pix * 4 + k] * hb[(size_t)q * HIDC + ch];
        }
        Hs[pix * 68 + ch] = a;
    }
    __syncthreads();

    int d = tid & 127;
    float wreg[HIDC];
#pragma unroll
    for (int h = 0; h < HIDC; h++) wreg[h] = w2s[d * 65 + h];
    float bd = b2[d];

#pragma unroll 4
    for (int pass = 0; pass < 32; pass++) {
        int pix = pass * 2 + (tid >> 7);
        int gp = p0 + pix;
        float acc = wss[pix] * bd;
        const float4* hv = (const float4*)&Hs[pix * 68];
#pragma unroll
        for (int h4 = 0; h4 < 16; h4++) {
            float4 hvv = hv[h4];
            acc = fmaf(wreg[h4 * 4 + 0], hvv.x, acc);
            acc = fmaf(wreg[h4 * 4 + 1], hvv.y, acc);
            acc = fmaf(wreg[h4 * 4 + 2], hvv.z, acc);
            acc = fmaf(wreg[h4 * 4 + 3], hvv.w, acc);
        }
        if (gp < NPIX)
            g_Fh[((size_t)ib * NPIX + gp) * FEATC + d] = __float2half_rn(acc);
    }
}

// ---------------- K4: single-term fp16 HMMA GEMM, 128x128, fp16 C (R11 form) ----------------
#define SA_HI 0
#define SBH_OFF 32768
#define GEMM_SMEM 65536
__device__ __forceinline__ uint32_t sw_off(int r, int c16) {
    return (uint32_t)(r * 256 + ((((c16 ^ r) & 7)) | (c16 & 8)) * 16);
}
__device__ __forceinline__ uint32_t smem_u32(const void* p) {
    uint32_t a;
    asm("{ .reg .u64 t; cvta.to.shared.u64 t, %1; cvt.u32.u64 %0, t; }" : "=r"(a) : "l"(p));
    return a;
}
#define LDSM_X4(R0, R1, R2, R3, addr)                                             \
    asm volatile("ldmatrix.sync.aligned.m8n8.x4.shared.b16 {%0,%1,%2,%3}, [%4];"  \
                 : "=r"(R0), "=r"(R1), "=r"(R2), "=r"(R3) : "r"(addr))
#define HMMA16816(D, A0, A1, A2, A3, B0, B1)                                      \
    asm volatile("mma.sync.aligned.m16n8k16.row.col.f32.f16.f16.f32 "             \
                 "{%0,%1,%2,%3}, {%4,%5,%6,%7}, {%8,%9}, {%0,%1,%2,%3};\n"        \
                 : "+f"(D[0]), "+f"(D[1]), "+f"(D[2]), "+f"(D[3])                 \
                 : "r"(A0), "r"(A1), "r"(A2), "r"(A3), "r"(B0), "r"(B1))

__global__ __launch_bounds__(256, 2) void gemm_hmma_kernel() {
    extern __shared__ char smem[];
    uint32_t sb = smem_u32(smem);
    int z = blockIdx.z;
    int mat = z >> 2, b = z & 3;
    size_t baseA = (size_t)((mat * 2)     * 4 + b) * NPIX * FEATC;
    size_t baseB = (size_t)((mat * 2 + 1) * 4 + b) * NPIX * FEATC;
    __half* C = g_M + (size_t)z * MSIZE;
    int n0 = blockIdx.y * 128, m0 = blockIdx.x * 128;
    int tid = threadIdx.x;
    int wid = tid >> 5, lane = tid & 31;
    int wr = wid >> 2, wc = wid & 3;

    {
        const uint4* srcA = (const uint4*)(g_Fh + baseA);
        const uint4* srcB = (const uint4*)(g_Fh + baseB);
#pragma unroll
        for (int i = 0; i < 8; i++) {
            int slot = tid + i * 256;
            int c16 = slot & 15, row = slot >> 4;
            int gr = n0 + row, gm = m0 + row;
            uint4 va = make_uint4(0, 0, 0, 0), vb = va;
            if (gr < NPIX) va = srcA[gr * 16 + c16];
            if (gm < NPIX) vb = srcB[gm * 16 + c16];
            uint32_t o = sw_off(row, c16);
            *(uint4*)(smem + SA_HI  + o) = va;
            *(uint4*)(smem + SBH_OFF + o) = vb;
        }
    }
    __syncthreads();

    float acc[4][4][4];
#pragma unroll
    for (int u = 0; u < 4; u++)
#pragma unroll
        for (int v = 0; v < 4; v++)
#pragma unroll
            for (int r = 0; r < 4; r++) acc[u][v][r] = 0.f;

    int a_row_l = ((lane >> 3) & 1) * 8 + (lane & 7);
    int a_c16_l = (lane >> 4);
    int b_row_l = ((lane >> 4) * 8) + (lane & 7);
    int b_c16_l = ((lane >> 3) & 1);

#pragma unroll
    for (int kt = 0; kt < 8; kt++) {
        uint32_t ah[4][4], bh[4][2];
#pragma unroll
        for (int mt = 0; mt < 4; mt++) {
            uint32_t off = sw_off(wr * 64 + mt * 16 + a_row_l, 2 * kt + a_c16_l);
            LDSM_X4(ah[mt][0], ah[mt][1], ah[mt][2], ah[mt][3], sb + SA_HI + off);
        }
#pragma unroll
        for (int np = 0; np < 2; np++) {
            uint32_t off = sw_off(wc * 32 + np * 16 + b_row_l, 2 * kt + b_c16_l);
            LDSM_X4(bh[np * 2][0], bh[np * 2][1], bh[np * 2 + 1][0], bh[np * 2 + 1][1], sb + SBH_OFF + off);
        }
#pragma unroll
        for (int mt = 0; mt < 4; mt++)
#pragma unroll
            for (int nt = 0; nt < 4; nt++)
                HMMA16816(acc[mt][nt], ah[mt][0], ah[mt][1], ah[mt][2], ah[mt][3], bh[nt][0], bh[nt][1]);
    }

    int g = lane >> 2, t4 = lane & 3;
#pragma unroll
    for (int mt = 0; mt < 4; mt++) {
        int r0 = n0 + wr * 64 + mt * 16 + g;
#pragma unroll
        for (int nt = 0; nt < 4; nt++) {
            int col = m0 + wc * 32 + nt * 8 + 2 * t4;
            if (col < NPIX) {
                if (r0 < NPIX)
                    *(__half2*)&C[(size_t)r0 * NPIX + col] = __floats2half2_rn(acc[mt][nt][0], acc[mt][nt][1]);
                if (r0 + 8 < NPIX)
                    *(__half2*)&C[(size_t)(r0 + 8) * NPIX + col] = __floats2half2_rn(acc[mt][nt][2], acc[mt][nt][3]);
            }
        }
    }

    // ---- fused per-tile softmax stats ----
    __syncthreads();
    float* s_a   = (float*)smem;
    float* s_fin = (float*)smem + 512;

    if (mat == 0) {
        float rmx[4][2];
#pragma unroll
        for (int mt = 0; mt < 4; mt++)
#pragma unroll
            for (int h = 0; h < 2; h++) {
                float v = -1e30f;
#pragma unroll
                for (int nt = 0; nt < 4; nt++)
#pragma unroll
                    for (int k = 0; k < 2; k++) {
                        int col = m0 + wc * 32 + nt * 8 + 2 * t4 + k;
                        float x = (col < NPIX) ? acc[mt][nt][h * 2 + k] : -1e30f;
                        v = fmaxf(v, x);
                    }
                rmx[mt][h] = v;
            }
#pragma unroll
        for (int o = 1; o < 4; o <<= 1)
#pragma unroll
            for (int mt = 0; mt < 4; mt++)
#pragma unroll
                for (int h = 0; h < 2; h++)
                    rmx[mt][h] = fmaxf(rmx[mt][h], __shfl_xor_sync(0xffffffffu, rmx[mt][h], o));
        if (t4 == 0)
#pragma unroll
            for (int mt = 0; mt < 4; mt++)
#pragma unroll
                for (int h = 0; h < 2; h++)
                    s_a[wc * 128 + wr * 64 + mt * 16 + h * 8 + g] = rmx[mt][h];
        __syncthreads();
        if (tid < 128)
            s_fin[tid] = fmaxf(fmaxf(s_a[tid], s_a[128 + tid]), fmaxf(s_a[256 + tid], s_a[384 + tid]));
        __syncthreads();
        float rsm[4][2];
#pragma unroll
        for (int mt = 0; mt < 4; mt++)
#pragma unroll
            for (int h = 0; h < 2; h++) {
                float fm = s_fin[wr * 64 + mt * 16 + h * 8 + g];
                float sa = 0.f;
#pragma unroll
                for (int nt = 0; nt < 4; nt++)
#pragma unroll
                    for (int k = 0; k < 2; k++) {
                        int col = m0 + wc * 32 + nt * 8 + 2 * t4 + k;
                        float x = (col < NPIX) ? acc[mt][nt][h * 2 + k] : -1e30f;
                        sa += fexp(x - fm);
                    }
                rsm[mt][h] = sa;
            }
#pragma unroll
        for (int o = 1; o < 4; o <<= 1)
#pragma unroll
            for (int mt = 0; mt < 4; mt++)
#pragma unroll
                for (int h = 0; h < 2; h++)
                    rsm[mt][h] += __shfl_xor_sync(0xffffffffu, rsm[mt][h], o);
        __syncthreads();
        if (t4 == 0)
#pragma unroll
            for (int mt = 0; mt < 4; mt++)
#pragma unroll
                for (int h = 0; h < 2; h++)
                    s_a[wc * 128 + wr * 64 + mt * 16 + h * 8 + g] = rsm[mt][h];
        __syncthreads();
        if (tid < 128) {
            int n = n0 + tid;
            if (n < NPIX) {
                int o = (blockIdx.x * 4 + b) * NPIX + n;
                g_rmax_p[o] = s_fin[tid];
                g_rsum_p[o] = s_a[tid] + s_a[128 + tid] + s_a[256 + tid] + s_a[384 + tid];
            }
        }
    } else {
        float cmx[4][2];
#pragma unroll
        for (int nt = 0; nt < 4; nt++)
#pragma unroll
            for (int k = 0; k < 2; k++) {
                float v = -1e30f;
#pragma unroll
                for (int mt = 0; mt < 4; mt++)
#pragma unroll
                    for (int h = 0; h < 2; h++) {
                        int row = n0 + wr * 64 + mt * 16 + h * 8 + g;
                        float x = (row < NPIX) ? acc[mt][nt][h * 2 + k] : -1e30f;
                        v = fmaxf(v, x);
                    }
                cmx[nt][k] = v;
            }
#pragma unroll
        for (int o = 4; o < 32; o <<= 1)
#pragma unroll
            for (int nt = 0; nt < 4; nt++)
#pragma unroll
                for (int k = 0; k < 2; k++)
                    cmx[nt][k] = fmaxf(cmx[nt][k], __shfl_xor_sync(0xffffffffu, cmx[nt][k], o));
        if (g == 0)
#pragma unroll
            for (int nt = 0; nt < 4; nt++)
#pragma unroll
                for (int k = 0; k < 2; k++)
                    s_a[wr * 128 + wc * 32 + nt * 8 + 2 * t4 + k] = cmx[nt][k];
        __syncthreads();
        if (tid < 128)
            s_fin[tid] = fmaxf(fmaxf(s_a[tid], s_a[128 + tid]), fmaxf(s_a[256 + tid], s_a[384 + tid]));
        __syncthreads();
        float csm[4][2];
#pragma unroll
        for (int nt = 0; nt < 4; nt++)
#pragma unroll
            for (int k = 0; k < 2; k++) {
                float fm = s_fin[wc * 32 + nt * 8 + 2 * t4 + k];
                float sa = 0.f;
#pragma unroll
                for (int mt = 0; mt < 4; mt++)
#pragma unroll
                    for (int h = 0; h < 2; h++) {
                        int row = n0 + wr * 64 + mt * 16 + h * 8 + g;
                        float x = (row < NPIX) ? acc[mt][nt][h * 2 + k] : -1e30f;
                        sa += fexp(x - fm);
                    }
                csm[nt][k] = sa;
            }
#pragma unroll
        for (int o = 4; o < 32; o <<= 1)
#pragma unroll
            for (int nt = 0; nt < 4; nt++)
#pragma unroll
                for (int k = 0; k < 2; k++)
                    csm[nt][k] += __shfl_xor_sync(0xffffffffu, csm[nt][k], o);
        __syncthreads();
        if (g == 0)
#pragma unroll
            for (int nt = 0; nt < 4; nt++)
#pragma unroll
                for (int k = 0; k < 2; k++)
                    s_a[wr * 128 + wc * 32 + nt * 8 + 2 * t4 + k] = csm[nt][k];
        __syncthreads();
        if (tid < 128) {
            int m = m0 + tid;
            if (m < NPIX) {
                int o = (blockIdx.y * 4 + b) * NPIX + m;
                g_cmax_p[o] = s_fin[tid];
                g_csum_p[o] = s_a[tid] + s_a[128 + tid] + s_a[256 + tid] + s_a[384 + tid];
            }
        }
    }
}

// ---------------- K5: merge row+col partials (fused) ----------------
__global__ void merge_kernel() {
    int idx = blockIdx.x * blockDim.x + threadIdx.x;
    int which = idx / (4 * NPIX);
    int sub = idx % (4 * NPIX);
    if (idx >= 8 * NPIX) return;
    if (which == 0) {
        float mx = -1e30f;
#pragma unroll
        for (int t = 0; t < NTIL; t++) mx = fmaxf(mx, g_rmax_p[t * 4 * NPIX + sub]);
        float s = 0.f;
#pragma unroll
        for (int t = 0; t < NTIL; t++)
            s += g_rsum_p[t * 4 * NPIX + sub] * fexp(g_rmax_p[t * 4 * NPIX + sub] - mx);
        g_hmax[sub] = mx;
        g_hs[sub]   = 1.f / (s + 1e-4f);
    } else {
        float mx = -1e30f;
#pragma unroll
        for (int t = 0; t < NTIL; t++) mx = fmaxf(mx, g_cmax_p[t * 4 * NPIX + sub]);
        float s = 0.f;
#pragma unroll
        for (int t = 0; t < NTIL; t++)
            s += g_csum_p[t * 4 * NPIX + sub] * fexp(g_cmax_p[t * 4 * NPIX + sub] - mx);
        g_vmax[sub] = mx;
        g_vs[sub]   = 1.f / (s + 1e-4f);
    }
}

// ---------------- K6: S[b,m] partials, half2 loads + 16 n-segments ----------------
__global__ void spart_kernel() {
    int m2 = blockIdx.x * 256 + threadIdx.x;   // half2 index (2 m's per thread)
    int b = blockIdx.y, seg = blockIdx.z;
    if (m2 >= NPIX / 2) return;
    const __half2* Mh = (const __half2*)(g_M + (size_t)b * MSIZE);
    const __half2* Mv = (const __half2*)(g_M + (size_t)(4 + b) * MSIZE);
    int m = 2 * m2;
    float vm0 = g_vmax[b * NPIX + m], vm1 = g_vmax[b * NPIX + m + 1];
    float s0 = 0.f, s1 = 0.f;
    int n0 = seg * SEGN;
    const int RW = NPIX / 2;                   // half2 row stride
    for (int nb = 0; nb < SEGN; nb += 5) {     // 225 = 45 x 5
        float2 av[5], cv[5];
        float hm[5], hw[5];
#pragma unroll
        for (int j = 0; j < 5; j++) {
            int n = n0 + nb + j;
            av[j] = __half22float2(__ldcs(&Mv[(size_t)n * RW + m2]));
            cv[j] = __half22float2(__ldcs(&Mh[(size_t)n * RW + m2]));
            hm[j] = g_hmax[b * NPIX + n];
            hw[j] = g_hs[b * NPIX + n];
        }
#pragma unroll
        for (int j = 0; j < 5; j++) {
            float base0 = av[j].x + cv[j].x - hm[j];
            float base1 = av[j].y + cv[j].y - hm[j];
            s0 = fmaf(fexp(base0 - vm0), hw[j], s0);
            s1 = fmaf(fexp(base1 - vm1), hw[j], s1);
        }
    }
    *(float2*)&g_Spart[(seg * 4 + b) * NPIX + m] = make_float2(s0, s1);
}

// ---------------- K7a: parallel log partials ----------------
__global__ void fpart_kernel() {
    __shared__ float red[256];
    int blk = blockIdx.x;
    int t = threadIdx.x;
    int base = blk * (4 * NPIX / FBLK);
    float acc = 0.f;
    if (t < 240) {
        int idx = base + t;
        int b = idx / NPIX, m = idx % NPIX;
        float S = 0.f;
#pragma unroll
        for (int seg = 0; seg < SEG; seg++) S += g_Spart[(seg * 4 + b) * NPIX + m];
        acc = logf(S * g_vs[idx] + 1e-4f);
    }
    red[t] = acc; __syncthreads();
    for (int s = 128; s > 0; s >>= 1) { if (t < s) red[t] += red[t + s]; __syncthreads(); }
    if (t == 0) g_fpart[blk] = red[0];
}

// ---------------- K7b: deterministic final merge ----------------
__global__ void final_kernel(float* __restrict__ out) {
    __shared__ float red[64];
    int t = threadIdx.x;
    float acc = (t < FBLK) ? g_fpart[t] : 0.f;
    red[t] = acc; __syncthreads();
    for (int s = 32; s > 0; s >>= 1) { if (t < s) red[t] += red[t + s]; __syncthreads(); }
    if (t == 0) out[0] = red[0] * (1.f / (4.f * NPIX));
}

// ---------------- launch ----------------
extern "C" void kernel_launch(void* const* d_in, const int* in_sizes, int n_in,
                              void* d_out, int out_size) {
    const float* input_a = (const float*)d_in[0];
    const float* input_b = (const float*)d_in[1];
    const float* w1      = (const float*)d_in[2];
    const float* b1      = (const float*)d_in[3];
    const float* w2      = (const float*)d_in[4];
    const float* b2      = (const float*)d_in[5];
    const float* noise   = (const float*)d_in[6];
    const int*   u_roll  = (const int*)d_in[7];
    const int*   v_roll  = (const int*)d_in[8];
    const int*   swap    = (const int*)d_in[9];
    float* out = (float*)d_out;

    cudaFuncSetAttribute(gemm_hmma_kernel, cudaFuncAttributeMaxDynamicSharedMemorySize, GEMM_SMEM);
    cudaFuncSetAttribute(bwdconv1_kernel, cudaFuncAttributeMaxDynamicSharedMemorySize, BW_SMEM);

    fwd_sample_kernel<<<(16 * 3 * NPIX + 255) / 256, 256>>>(input_a, input_b, noise, swap, u_roll, v_roll);
    conv3_kernel<<<dim3(NPIX / 4, 16), 256>>>(w1, b1);
    bwdconv1_kernel<<<dim3((NPIX + PIXB - 1) / PIXB, 16), 256, BW_SMEM>>>(w2, b2, noise, swap, u_roll, v_roll);
    gemm_hmma_kernel<<<dim3(NTIL, NTIL, 8), 256, GEMM_SMEM>>>();
    merge_kernel<<<(8 * NPIX + 255) / 256, 256>>>();
    spart_kernel<<<dim3((NPIX / 2 + 255) / 256, 4, SEG), 256>>>();
    fpart_kernel<<<FBLK, 256>>>();
    final_kernel<<<1, 64>>>(out);
}